// round 11
// baseline (speedup 1.0000x reference)
#include <cuda_runtime.h>
#include <cuda_bf16.h>
#include <cstdint>
#include <math.h>

#define SEQLEN   2048
#define DIM      4096
#define NHEADS   32
#define NKV      8
#define HD       128
#define WINDOW   4096
#define QSTRIDE  (NHEADS * HD)   // 4096
#define KSTRIDE  (NKV * HD)      // 1024
#define NQKV     (QSTRIDE + 2 * KSTRIDE)   // 6144
#define ATT_SCALE 0.08838834764831843f
#define DESC14   6.103515625e-05f   // 2^-14

// ==================== scratch ==============================================
__device__ __nv_bfloat16 g_xh [(size_t)SEQLEN * DIM];
__device__ uint8_t       g_x8h[(size_t)SEQLEN * DIM];
__device__ uint8_t       g_x8l[(size_t)SEQLEN * DIM];
__device__ __nv_bfloat16 g_wh [(size_t)NQKV * DIM];
__device__ uint8_t       g_w8h[(size_t)NQKV * DIM];
__device__ uint8_t       g_w8l[(size_t)NQKV * DIM];
__device__ __nv_bfloat16 g_woh [(size_t)DIM * QSTRIDE];
__device__ uint8_t       g_wo8h[(size_t)DIM * QSTRIDE];
__device__ uint8_t       g_wo8l[(size_t)DIM * QSTRIDE];
__device__ __nv_bfloat16 g_aoh [(size_t)SEQLEN * QSTRIDE];
__device__ uint8_t       g_ao8h[(size_t)SEQLEN * QSTRIDE];
__device__ uint8_t       g_ao8l[(size_t)SEQLEN * QSTRIDE];
__device__ __nv_bfloat16 g_qh[(size_t)SEQLEN * QSTRIDE];
__device__ __nv_bfloat16 g_ql[(size_t)SEQLEN * QSTRIDE];
__device__ __nv_bfloat16 g_kh[(size_t)SEQLEN * KSTRIDE];
__device__ __nv_bfloat16 g_kl[(size_t)SEQLEN * KSTRIDE];
__device__ __nv_bfloat16 g_vh[(size_t)SEQLEN * KSTRIDE];
__device__ __nv_bfloat16 g_vl[(size_t)SEQLEN * KSTRIDE];

// ==================== helpers ===============================================
__device__ __forceinline__ void mma16816(float* c, const uint32_t* a,
                                         uint32_t b0, uint32_t b1) {
    asm volatile(
        "mma.sync.aligned.m16n8k16.row.col.f32.bf16.bf16.f32 "
        "{%0,%1,%2,%3}, {%4,%5,%6,%7}, {%8,%9}, {%0,%1,%2,%3};"
        : "+f"(c[0]), "+f"(c[1]), "+f"(c[2]), "+f"(c[3])
        : "r"(a[0]), "r"(a[1]), "r"(a[2]), "r"(a[3]), "r"(b0), "r"(b1));
}
__device__ __forceinline__ void mma_fp8(float* d, const uint32_t* a,
                                        uint32_t b0, uint32_t b1) {
    asm volatile(
        "mma.sync.aligned.m16n8k32.row.col.f32.e4m3.e4m3.f32 "
        "{%0,%1,%2,%3}, {%4,%5,%6,%7}, {%8,%9}, {%0,%1,%2,%3};"
        : "+f"(d[0]), "+f"(d[1]), "+f"(d[2]), "+f"(d[3])
        : "r"(a[0]), "r"(a[1]), "r"(a[2]), "r"(a[3]), "r"(b0), "r"(b1));
}
__device__ __forceinline__ void cp_async16(void* smem_dst, const void* gmem_src) {
    uint32_t sa;
    asm("{ .reg .u64 t; cvta.to.shared.u64 t, %1; cvt.u32.u64 %0, t; }"
        : "=r"(sa) : "l"(smem_dst));
    asm volatile("cp.async.cg.shared.global [%0], [%1], 16;" :: "r"(sa), "l"(gmem_src));
}
#define CP_COMMIT() asm volatile("cp.async.commit_group;" ::: "memory")
__device__ __forceinline__ void ldsm_x4_t(uint32_t* r, uint32_t addr) {
    asm volatile("ldmatrix.sync.aligned.m8n8.x4.trans.shared.b16 {%0,%1,%2,%3}, [%4];"
        : "=r"(r[0]), "=r"(r[1]), "=r"(r[2]), "=r"(r[3]) : "r"(addr));
}
__device__ __forceinline__ uint32_t smem_u32(const void* p) {
    uint32_t a;
    asm("{ .reg .u64 t; cvta.to.shared.u64 t, %1; cvt.u32.u64 %0, t; }"
        : "=r"(a) : "l"(p));
    return a;
}
__device__ __forceinline__ uint32_t pack2(float a, float b) {
    __nv_bfloat162 t = __floats2bfloat162_rn(a, b);
    return *(uint32_t*)&t;
}
__device__ __forceinline__ uint16_t e4m3x2(float hi_v, float lo_v) {
    // byte0 (low addr) = lo_v, byte1 = hi_v
    uint16_t r;
    asm("cvt.rn.satfinite.e4m3x2.f32 %0, %1, %2;" : "=h"(r) : "f"(hi_v), "f"(lo_v));
    return r;
}
__device__ __forceinline__ void store_hilo(__nv_bfloat16* H, __nv_bfloat16* L,
                                           size_t off, float a, float b) {
    float ha = __bfloat162float(__float2bfloat16_rn(a));
    float hb = __bfloat162float(__float2bfloat16_rn(b));
    *(uint32_t*)&H[off] = pack2(ha, hb);
    *(uint32_t*)&L[off] = pack2(a - ha, b - hb);
}

// ==================== merged fp32 -> (bf16 h, fp8 h, fp8 l) split ===========
#define SPLIT_R0 1048576u                     // x
#define SPLIT_R1 (SPLIT_R0 + 2097152u)        // wq
#define SPLIT_R2 (SPLIT_R1 + 524288u)         // wk
#define SPLIT_R3 (SPLIT_R2 + 524288u)         // wv
#define SPLIT_R4 (SPLIT_R3 + 2097152u)        // wo
#define SPLIT_TOTAL SPLIT_R4

__global__ void split_all_kernel(const float* __restrict__ x,
                                 const float* __restrict__ wq,
                                 const float* __restrict__ wk,
                                 const float* __restrict__ wv,
                                 const float* __restrict__ wo,
                                 __nv_bfloat16* __restrict__ xh,
                                 uint8_t* __restrict__ x8h, uint8_t* __restrict__ x8l,
                                 __nv_bfloat16* __restrict__ wh,
                                 uint8_t* __restrict__ w8h, uint8_t* __restrict__ w8l,
                                 __nv_bfloat16* __restrict__ woh,
                                 uint8_t* __restrict__ wo8h, uint8_t* __restrict__ wo8l)
{
    uint32_t i = blockIdx.x * blockDim.x + threadIdx.x;
    if (i >= SPLIT_TOTAL) return;

    const float* src;
    __nv_bfloat16* hb;
    uint8_t *f8h, *f8l;
    uint32_t j;
    float s1, s2;
    if (i < SPLIT_R0) {
        src = x;  hb = xh;  f8h = x8h; f8l = x8l; j = i;
        s1 = 1.0f; s2 = 512.0f;
    } else if (i < SPLIT_R1) {
        src = wq; hb = wh;  f8h = w8h; f8l = w8l; j = i - SPLIT_R0;
        s1 = 32.0f; s2 = 16384.0f;
    } else if (i < SPLIT_R2) {
        src = wk; hb = wh + (size_t)QSTRIDE * DIM;
        f8h = w8h + (size_t)QSTRIDE * DIM; f8l = w8l + (size_t)QSTRIDE * DIM;
        j = i - SPLIT_R1; s1 = 32.0f; s2 = 16384.0f;
    } else if (i < SPLIT_R3) {
        src = wv; hb = wh + (size_t)(QSTRIDE + KSTRIDE) * DIM;
        f8h = w8h + (size_t)(QSTRIDE + KSTRIDE) * DIM;
        f8l = w8l + (size_t)(QSTRIDE + KSTRIDE) * DIM;
        j = i - SPLIT_R2; s1 = 32.0f; s2 = 16384.0f;
    } else {
        src = wo; hb = woh; f8h = wo8h; f8l = wo8l; j = i - SPLIT_R3;
        s1 = 32.0f; s2 = 16384.0f;
    }

    float4 v0 = ((const float4*)src)[2 * (size_t)j];
    float4 v1 = ((const float4*)src)[2 * (size_t)j + 1];
    float f[8] = { v0.x, v0.y, v0.z, v0.w, v1.x, v1.y, v1.z, v1.w };
    float hv[8], lv[8];
    uint32_t hw[4];
#pragma unroll
    for (int k = 0; k < 8; k++) {
        hv[k] = __bfloat162float(__float2bfloat16_rn(f[k]));
        lv[k] = f[k] - hv[k];
    }
#pragma unroll
    for (int k = 0; k < 4; k++) hw[k] = pack2(hv[2 * k], hv[2 * k + 1]);
    ((uint4*)hb)[j] = make_uint4(hw[0], hw[1], hw[2], hw[3]);

    uint32_t h8a = (uint32_t)e4m3x2(f[1] * s1, f[0] * s1) |
                   ((uint32_t)e4m3x2(f[3] * s1, f[2] * s1) << 16);
    uint32_t h8b = (uint32_t)e4m3x2(f[5] * s1, f[4] * s1) |
                   ((uint32_t)e4m3x2(f[7] * s1, f[6] * s1) << 16);
    ((uint2*)f8h)[j] = make_uint2(h8a, h8b);
    uint32_t l8a = (uint32_t)e4m3x2(lv[1] * s2, lv[0] * s2) |
                   ((uint32_t)e4m3x2(lv[3] * s2, lv[2] * s2) << 16);
    uint32_t l8b = (uint32_t)e4m3x2(lv[5] * s2, lv[4] * s2) |
                   ((uint32_t)e4m3x2(lv[7] * s2, lv[6] * s2) << 16);
    ((uint2*)f8l)[j] = make_uint2(l8a, l8b);
}

// ==================== bf16-main + fp8-correction GEMM =======================
// C[M,N] = A @ B^T ; main Ah*Bh in bf16 HMMA, corrections in fp8 QMMA.
#define GPAD     40
#define BT16     10240                 // bf16 subtile bytes (128 x 80B)
#define F8S      48                    // fp8 row stride bytes
#define BT8      6144                  // fp8 subtile bytes (128 x 48B)
#define STAGE_B  (2 * BT16 + 4 * BT8)  // 45056
#define GSMEM_BYTES (2 * STAGE_B)      // 90112

__global__ __launch_bounds__(256, 2) void gemm_fused(
    const __nv_bfloat16* __restrict__ Ah,
    const uint8_t* __restrict__ A8h, const uint8_t* __restrict__ A8l,
    const __nv_bfloat16* __restrict__ Bh,
    const uint8_t* __restrict__ B8h, const uint8_t* __restrict__ B8l,
    float* __restrict__ C,
    const float* __restrict__ cf, const float* __restrict__ sf,
    __nv_bfloat16* __restrict__ Qh, __nv_bfloat16* __restrict__ Ql,
    __nv_bfloat16* __restrict__ Kh, __nv_bfloat16* __restrict__ Kl,
    __nv_bfloat16* __restrict__ Vh, __nv_bfloat16* __restrict__ Vl,
    float* __restrict__ CK, float* __restrict__ CV,
    int N, int K, int mode)
{
    extern __shared__ char sm[];
    const int tid  = threadIdx.x;
    const int wid  = tid >> 5;
    const int lane = tid & 31;
    const int g    = lane >> 2;
    const int tg   = lane & 3;
    const int wm   = wid & 1;
    const int wn   = wid >> 1;
    const int bm   = blockIdx.y << 7;
    const int bn   = blockIdx.x << 7;

    const uint8_t* f8src[4] = { A8h, A8l, B8h, B8l };

    auto load_stage = [&](int s, int k0) {
        char* base = sm + s * STAGE_B;
#pragma unroll
        for (int t = 0; t < 8; t++) {
            int id = tid + (t << 8);
            if (id < 1024) {
                int sub = id >> 9;          // 0=Ah, 1=Bh
                int idx = id & 511;
                int r = idx >> 2, c = idx & 3;
                const __nv_bfloat16* gsrc = sub ? Bh : Ah;
                int row0 = sub ? bn : bm;
                cp_async16(base + sub * BT16 + r * 80 + c * 16,
                           gsrc + (size_t)(row0 + r) * K + k0 + c * 8);
            } else {
                int sub = (id - 1024) >> 8; // 0..3
                int idx = id & 255;
                int r = idx >> 1, c = idx & 1;
                int row0 = (sub < 2) ? bm : bn;
                cp_async16(base + 2 * BT16 + sub * BT8 + r * F8S + c * 16,
                           f8src[sub] + (size_t)(row0 + r) * K + k0 + c * 16);
            }
        }
        CP_COMMIT();
    };

    float acc[4][4][4];
#pragma unroll
    for (int m = 0; m < 4; m++)
#pragma unroll
        for (int n = 0; n < 4; n++)
#pragma unroll
            for (int k = 0; k < 4; k++) acc[m][n][k] = 0.f;

    const int NIT = K >> 5;
    load_stage(0, 0);

    for (int it = 0; it < NIT; it++) {
        asm volatile("cp.async.wait_group 0;" ::: "memory");
        __syncthreads();
        if (it + 1 < NIT) load_stage((it + 1) & 1, (it + 1) << 5);

        const char* base = sm + (it & 1) * STAGE_B;
        const __nv_bfloat16* Ahs = (const __nv_bfloat16*)base;
        const __nv_bfloat16* Bhs = (const __nv_bfloat16*)(base + BT16);
        const char* A8hs = base + 2 * BT16;
        const char* A8ls = A8hs + BT8;
        const char* B8hs = A8ls + BT8;
        const char* B8ls = B8hs + BT8;

        // ---- fp8 B fragments (whole K32) ----
        uint32_t c8h[4][2], c8l[4][2];
#pragma unroll
        for (int n = 0; n < 4; n++) {
            int nr = wn * 32 + n * 8 + g;
            c8h[n][0] = *(const uint32_t*)(B8hs + nr * F8S + tg * 4);
            c8h[n][1] = *(const uint32_t*)(B8hs + nr * F8S + 16 + tg * 4);
            c8l[n][0] = *(const uint32_t*)(B8ls + nr * F8S + tg * 4);
            c8l[n][1] = *(const uint32_t*)(B8ls + nr * F8S + 16 + tg * 4);
        }

        // ---- fp8 corrections: acc += 2^-14 * (a8h*b8l + a8l*b8h) ----
#pragma unroll
        for (int m = 0; m < 4; m++) {
            int mr = wm * 64 + m * 16;
            uint32_t a8h[4], a8l[4];
            a8h[0] = *(const uint32_t*)(A8hs + (mr + g) * F8S + tg * 4);
            a8h[1] = *(const uint32_t*)(A8hs + (mr + 8 + g) * F8S + tg * 4);
            a8h[2] = *(const uint32_t*)(A8hs + (mr + g) * F8S + 16 + tg * 4);
            a8h[3] = *(const uint32_t*)(A8hs + (mr + 8 + g) * F8S + 16 + tg * 4);
            a8l[0] = *(const uint32_t*)(A8ls + (mr + g) * F8S + tg * 4);
            a8l[1] = *(const uint32_t*)(A8ls + (mr + 8 + g) * F8S + tg * 4);
            a8l[2] = *(const uint32_t*)(A8ls + (mr + g) * F8S + 16 + tg * 4);
            a8l[3] = *(const uint32_t*)(A8ls + (mr + 8 + g) * F8S + 16 + tg * 4);
#pragma unroll
            for (int n = 0; n < 4; n++) {
                float D[4] = { 0.f, 0.f, 0.f, 0.f };
                mma_fp8(D, a8h, c8l[n][0], c8l[n][1]);
                mma_fp8(D, a8l, c8h[n][0], c8h[n][1]);
#pragma unroll
                for (int c = 0; c < 4; c++)
                    acc[m][n][c] = fmaf(DESC14, D[c], acc[m][n][c]);
            }
        }

        // ---- bf16 main term ----
#pragma unroll
        for (int ks = 0; ks < 32; ks += 16) {
            uint32_t bh[4][2];
#pragma unroll
            for (int n = 0; n < 4; n++) {
                int nr = wn * 32 + n * 8 + g;
                bh[n][0] = *(const uint32_t*)&Bhs[nr * GPAD + ks + 2 * tg];
                bh[n][1] = *(const uint32_t*)&Bhs[nr * GPAD + ks + 8 + 2 * tg];
            }
#pragma unroll
            for (int m = 0; m < 4; m++) {
                int mr = wm * 64 + m * 16;
                uint32_t ah[4];
                ah[0] = *(const uint32_t*)&Ahs[(mr + g)     * GPAD + ks + 2 * tg];
                ah[1] = *(const uint32_t*)&Ahs[(mr + 8 + g) * GPAD + ks + 2 * tg];
                ah[2] = *(const uint32_t*)&Ahs[(mr + g)     * GPAD + ks + 8 + 2 * tg];
                ah[3] = *(const uint32_t*)&Ahs[(mr + 8 + g) * GPAD + ks + 8 + 2 * tg];
#pragma unroll
                for (int n = 0; n < 4; n++)
                    mma16816(acc[m][n], ah, bh[n][0], bh[n][1]);
            }
        }
        __syncthreads();
    }

    if (mode == 0) {
#pragma unroll
        for (int m = 0; m < 4; m++) {
            int r0 = bm + wm * 64 + m * 16 + g;
#pragma unroll
            for (int n = 0; n < 4; n++) {
                int col = bn + wn * 32 + n * 8 + 2 * tg;
                *(float2*)&C[(size_t)r0 * N + col] =
                    make_float2(acc[m][n][0], acc[m][n][1]);
                *(float2*)&C[(size_t)(r0 + 8) * N + col] =
                    make_float2(acc[m][n][2], acc[m][n][3]);
            }
        }
    } else if (bn < QSTRIDE) {
        // ---- Q region: rope + scale + hi/lo split ----
#pragma unroll
        for (int m = 0; m < 4; m++) {
            int r0 = bm + wm * 64 + m * 16 + g;
#pragma unroll
            for (int n = 0; n < 4; n++) {
                int col = bn + wn * 32 + n * 8 + 2 * tg;
                int d = (col & 127) >> 1;
                float cA = cf[r0 * 64 + d], sA = sf[r0 * 64 + d];
                float u0 = (acc[m][n][0] * cA - acc[m][n][1] * sA) * ATT_SCALE;
                float v0 = (acc[m][n][0] * sA + acc[m][n][1] * cA) * ATT_SCALE;
                store_hilo(Qh, Ql, (size_t)r0 * QSTRIDE + col, u0, v0);
                float cB = cf[(r0 + 8) * 64 + d], sB = sf[(r0 + 8) * 64 + d];
                float u1 = (acc[m][n][2] * cB - acc[m][n][3] * sB) * ATT_SCALE;
                float v1 = (acc[m][n][2] * sB + acc[m][n][3] * cB) * ATT_SCALE;
                store_hilo(Qh, Ql, (size_t)(r0 + 8) * QSTRIDE + col, u1, v1);
            }
        }
    } else if (bn < QSTRIDE + KSTRIDE) {
        // ---- K region: rope + cache + hi/lo split ----
#pragma unroll
        for (int m = 0; m < 4; m++) {
            int r0 = bm + wm * 64 + m * 16 + g;
#pragma unroll
            for (int n = 0; n < 4; n++) {
                int colk = bn - QSTRIDE + wn * 32 + n * 8 + 2 * tg;
                int d = (colk & 127) >> 1;
                float cA = cf[r0 * 64 + d], sA = sf[r0 * 64 + d];
                float u0 = acc[m][n][0] * cA - acc[m][n][1] * sA;
                float v0 = acc[m][n][0] * sA + acc[m][n][1] * cA;
                *(float2*)&CK[(size_t)r0 * KSTRIDE + colk] = make_float2(u0, v0);
                store_hilo(Kh, Kl, (size_t)r0 * KSTRIDE + colk, u0, v0);
                float cB = cf[(r0 + 8) * 64 + d], sB = sf[(r0 + 8) * 64 + d];
                float u1 = acc[m][n][2] * cB - acc[m][n][3] * sB;
                float v1 = acc[m][n][2] * sB + acc[m][n][3] * cB;
                *(float2*)&CK[(size_t)(r0 + 8) * KSTRIDE + colk] = make_float2(u1, v1);
                store_hilo(Kh, Kl, (size_t)(r0 + 8) * KSTRIDE + colk, u1, v1);
            }
        }
    } else {
        // ---- V region: cache + hi/lo split ----
#pragma unroll
        for (int m = 0; m < 4; m++) {
            int r0 = bm + wm * 64 + m * 16 + g;
#pragma unroll
            for (int n = 0; n < 4; n++) {
                int colv = bn - QSTRIDE - KSTRIDE + wn * 32 + n * 8 + 2 * tg;
                *(float2*)&CV[(size_t)r0 * KSTRIDE + colv] =
                    make_float2(acc[m][n][0], acc[m][n][1]);
                store_hilo(Vh, Vl, (size_t)r0 * KSTRIDE + colv,
                           acc[m][n][0], acc[m][n][1]);
                *(float2*)&CV[(size_t)(r0 + 8) * KSTRIDE + colv] =
                    make_float2(acc[m][n][2], acc[m][n][3]);
                store_hilo(Vh, Vl, (size_t)(r0 + 8) * KSTRIDE + colv,
                           acc[m][n][2], acc[m][n][3]);
            }
        }
    }
}

// ==================== cache tail ============================================
__global__ void cache_tail_kernel(const float* __restrict__ cki,
                                  const float* __restrict__ cvi,
                                  float* __restrict__ cko,
                                  float* __restrict__ cvo)
{
    int idx = blockIdx.x * blockDim.x + threadIdx.x;
    if (idx >= (WINDOW - SEQLEN) * KSTRIDE) return;
    size_t off = (size_t)SEQLEN * KSTRIDE + idx;
    cko[off] = cki[off];
    cvo[off] = cvi[off];
}

// ==================== HMMA flash attention (R6-proven, fp8 ao epilogue) =====
#define SPAD      136
#define Q_ELEMS   (128 * SPAD)
#define KV_ELEMS  (64 * SPAD)
#define ATT_SMEM  ((2 * Q_ELEMS + 8 * KV_ELEMS) * 2)

__global__ __launch_bounds__(256, 1) void flash_mma(
    const __nv_bfloat16* __restrict__ Qhg, const __nv_bfloat16* __restrict__ Qlg,
    const __nv_bfloat16* __restrict__ Khg, const __nv_bfloat16* __restrict__ Klg,
    const __nv_bfloat16* __restrict__ Vhg, const __nv_bfloat16* __restrict__ Vlg,
    __nv_bfloat16* __restrict__ Ohg,
    uint8_t* __restrict__ O8h, uint8_t* __restrict__ O8l)
{
    extern __shared__ __nv_bfloat16 sb[];
    const int tid  = threadIdx.x;
    const int wid  = tid >> 5;
    const int lane = tid & 31;
    const int g    = lane >> 2;
    const int tg   = lane & 3;
    const int qb   = (int)(gridDim.x - 1 - blockIdx.x);
    const int h    = blockIdx.y;
    const int kvh  = h >> 2;
    const int q0   = qb << 7;
    const int mr   = wid << 4;

    __nv_bfloat16* Qhs = sb;
    __nv_bfloat16* Qls = sb + Q_ELEMS;
    __nv_bfloat16* KVs = sb + 2 * Q_ELEMS;
    const uint32_t sbase = smem_u32(sb);

    {
        const __nv_bfloat16* gq[2] = { Qhg, Qlg };
#pragma unroll
        for (int i = 0; i < 16; i++) {
            int id  = tid + (i << 8);
            int tsr = id >> 11, idx = id & 2047;
            int r = idx >> 4, c = idx & 15;
            cp_async16(sb + tsr * Q_ELEMS + r * SPAD + c * 8,
                       gq[tsr] + (size_t)(q0 + r) * QSTRIDE + h * HD + c * 8);
        }
        CP_COMMIT();
    }

    const int NT = 2 * qb + 2;
    const __nv_bfloat16* gkv[4] = { Khg, Klg, Vhg, Vlg };
    auto load_kv = [&](int t, int st) {
        __nv_bfloat16* base = KVs + st * 4 * KV_ELEMS;
#pragma unroll
        for (int i = 0; i < 16; i++) {
            int id  = tid + (i << 8);
            int sub = id >> 10, idx = id & 1023;
            int r = idx >> 4, c = idx & 15;
            cp_async16(base + sub * KV_ELEMS + r * SPAD + c * 8,
                       gkv[sub] + (size_t)(t * 64 + r) * KSTRIDE + kvh * HD + c * 8);
        }
        CP_COMMIT();
    };
    load_kv(0, 0);

    float m0 = -1e30f, m1 = -1e30f, l0 = 0.f, l1 = 0.f;
    float o[16][4];
#pragma unroll
    for (int n = 0; n < 16; n++)
#pragma unroll
        for (int c = 0; c < 4; c++) o[n][c] = 0.f;

    for (int t = 0; t < NT; t++) {
        if (t + 1 < NT) {
            load_kv(t + 1, (t + 1) & 1);
            asm volatile("cp.async.wait_group 1;" ::: "memory");
        } else {
            asm volatile("cp.async.wait_group 0;" ::: "memory");
        }
        __syncthreads();

        if (t * 64 <= q0 + mr + 15) {
            const __nv_bfloat16* Khs = KVs + (t & 1) * 4 * KV_ELEMS;
            const __nv_bfloat16* Kls = Khs + KV_ELEMS;
            const uint32_t vh_base = sbase +
                (uint32_t)(2 * Q_ELEMS + (t & 1) * 4 * KV_ELEMS + 2 * KV_ELEMS) * 2;
            const uint32_t vl_base = vh_base + KV_ELEMS * 2;

            float sc[8][4];
#pragma unroll
            for (int n = 0; n < 8; n++)
#pragma unroll
                for (int c = 0; c < 4; c++) sc[n][c] = 0.f;

#pragma unroll
            for (int k = 0; k < 8; k++) {
                int ks = k << 4;
                uint32_t qh[4], ql[4];
                qh[0] = *(const uint32_t*)&Qhs[(mr + g)     * SPAD + ks + 2 * tg];
                qh[1] = *(const uint32_t*)&Qhs[(mr + 8 + g) * SPAD + ks + 2 * tg];
                qh[2] = *(const uint32_t*)&Qhs[(mr + g)     * SPAD + ks + 8 + 2 * tg];
                qh[3] = *(const uint32_t*)&Qhs[(mr + 8 + g) * SPAD + ks + 8 + 2 * tg];
                ql[0] = *(const uint32_t*)&Qls[(mr + g)     * SPAD + ks + 2 * tg];
                ql[1] = *(const uint32_t*)&Qls[(mr + 8 + g) * SPAD + ks + 2 * tg];
                ql[2] = *(const uint32_t*)&Qls[(mr + g)     * SPAD + ks + 8 + 2 * tg];
                ql[3] = *(const uint32_t*)&Qls[(mr + 8 + g) * SPAD + ks + 8 + 2 * tg];
#pragma unroll
                for (int n = 0; n < 8; n++) {
                    uint32_t kh0, kh1, kl0, kl1;
                    kh0 = *(const uint32_t*)&Khs[(8 * n + g) * SPAD + ks + 2 * tg];
                    kh1 = *(const uint32_t*)&Khs[(8 * n + g) * SPAD + ks + 8 + 2 * tg];
                    kl0 = *(const uint32_t*)&Kls[(8 * n + g) * SPAD + ks + 2 * tg];
                    kl1 = *(const uint32_t*)&Kls[(8 * n + g) * SPAD + ks + 8 + 2 * tg];
                    mma16816(sc[n], qh, kh0, kh1);
                    mma16816(sc[n], qh, kl0, kl1);
                    mma16816(sc[n], ql, kh0, kh1);
                }
            }

            const int qi0 = q0 + mr + g, qi1 = qi0 + 8;
            if (t * 64 + 63 > q0 + mr) {
#pragma unroll
                for (int n = 0; n < 8; n++) {
                    int kj = t * 64 + 8 * n + 2 * tg;
                    if (kj     > qi0) sc[n][0] = -1e30f;
                    if (kj + 1 > qi0) sc[n][1] = -1e30f;
                    if (kj     > qi1) sc[n][2] = -1e30f;
                    if (kj + 1 > qi1) sc[n][3] = -1e30f;
                }
            }

            float mt0 = -1e30f, mt1 = -1e30f;
#pragma unroll
            for (int n = 0; n < 8; n++) {
                mt0 = fmaxf(mt0, fmaxf(sc[n][0], sc[n][1]));
                mt1 = fmaxf(mt1, fmaxf(sc[n][2], sc[n][3]));
            }
            mt0 = fmaxf(mt0, __shfl_xor_sync(0xffffffffu, mt0, 1));
            mt0 = fmaxf(mt0, __shfl_xor_sync(0xffffffffu, mt0, 2));
            mt1 = fmaxf(mt1, __shfl_xor_sync(0xffffffffu, mt1, 1));
            mt1 = fmaxf(mt1, __shfl_xor_sync(0xffffffffu, mt1, 2));
            float m0n = fmaxf(m0, mt0), m1n = fmaxf(m1, mt1);
            float c0 = __expf(m0 - m0n), c1 = __expf(m1 - m1n);
            float rs0 = 0.f, rs1 = 0.f;
#pragma unroll
            for (int n = 0; n < 8; n++) {
                sc[n][0] = __expf(sc[n][0] - m0n);
                sc[n][1] = __expf(sc[n][1] - m0n);
                sc[n][2] = __expf(sc[n][2] - m1n);
                sc[n][3] = __expf(sc[n][3] - m1n);
                rs0 += sc[n][0] + sc[n][1];
                rs1 += sc[n][2] + sc[n][3];
            }
            rs0 += __shfl_xor_sync(0xffffffffu, rs0, 1);
            rs0 += __shfl_xor_sync(0xffffffffu, rs0, 2);
            rs1 += __shfl_xor_sync(0xffffffffu, rs1, 1);
            rs1 += __shfl_xor_sync(0xffffffffu, rs1, 2);
            l0 = l0 * c0 + rs0;
            l1 = l1 * c1 + rs1;
            m0 = m0n; m1 = m1n;
#pragma unroll
            for (int n = 0; n < 16; n++) {
                o[n][0] *= c0; o[n][1] *= c0; o[n][2] *= c1; o[n][3] *= c1;
            }

            uint32_t ph[4][4], pl[4][4];
#pragma unroll
            for (int j = 0; j < 4; j++) {
                const float* A = sc[2 * j];
                const float* B = sc[2 * j + 1];
                float ah0 = __bfloat162float(__float2bfloat16_rn(A[0]));
                float ah1 = __bfloat162float(__float2bfloat16_rn(A[1]));
                float ah2 = __bfloat162float(__float2bfloat16_rn(A[2]));
                float ah3 = __bfloat162float(__float2bfloat16_rn(A[3]));
                float bh0 = __bfloat162float(__float2bfloat16_rn(B[0]));
                float bh1 = __bfloat162float(__float2bfloat16_rn(B[1]));
                float bh2 = __bfloat162float(__float2bfloat16_rn(B[2]));
                float bh3 = __bfloat162float(__float2bfloat16_rn(B[3]));
                ph[j][0] = pack2(ah0, ah1);
                ph[j][1] = pack2(ah2, ah3);
                ph[j][2] = pack2(bh0, bh1);
                ph[j][3] = pack2(bh2, bh3);
                pl[j][0] = pack2(A[0] - ah0, A[1] - ah1);
                pl[j][1] = pack2(A[2] - ah2, A[3] - ah3);
                pl[j][2] = pack2(B[0] - bh0, B[1] - bh1);
                pl[j][3] = pack2(B[2] - bh2, B[3] - bh3);
            }

            const uint32_t va = (uint32_t)(((lane & 15) * SPAD + ((lane >> 4) << 3)) * 2);
#pragma unroll
            for (int j = 0; j < 4; j++) {
                const uint32_t kvoff = va + (uint32_t)(16 * j * SPAD * 2);
#pragma unroll
                for (int u = 0; u < 8; u++) {
                    uint32_t vh[4], vl[4];
                    ldsm_x4_t(vh, vh_base + kvoff + u * 32);
                    ldsm_x4_t(vl, vl_base + kvoff + u * 32);
                    mma16816(o[2 * u],     ph[j], vh[0], vh[1]);
                    mma16816(o[2 * u],     ph[j], vl[0], vl[1]);
                    mma16816(o[2 * u],     pl[j], vh[0], vh[1]);
                    mma16816(o[2 * u + 1], ph[j], vh[2], vh[3]);
                    mma16816(o[2 * u + 1], ph[j], vl[2], vl[3]);
                    mma16816(o[2 * u + 1], pl[j], vh[2], vh[3]);
                }
            }
        }
        __syncthreads();
    }

    // ---- epilogue: normalize; emit bf16 h + fp8 h + fp8 l(scale 512) ----
    const float inv0 = 1.f / l0, inv1 = 1.f / l1;
    const int row0 = q0 + mr + g, row1 = row0 + 8;
#pragma unroll
    for (int n = 0; n < 16; n++) {
        int col = h * HD + 8 * n + 2 * tg;
        float f00 = o[n][0] * inv0, f01 = o[n][1] * inv0;
        float f10 = o[n][2] * inv1, f11 = o[n][3] * inv1;
        float h00 = __bfloat162float(__float2bfloat16_rn(f00));
        float h01 = __bfloat162float(__float2bfloat16_rn(f01));
        float h10 = __bfloat162float(__float2bfloat16_rn(f10));
        float h11 = __bfloat162float(__float2bfloat16_rn(f11));
        size_t off0 = (size_t)row0 * QSTRIDE + col;
        size_t off1 = (size_t)row1 * QSTRIDE + col;
        *(uint32_t*)&Ohg[off0] = pack2(h00, h01);
        *(uint32_t*)&Ohg[off1] = pack2(h10, h11);
        *(uint16_t*)&O8h[off0] = e4m3x2(f01, f00);
        *(uint16_t*)&O8h[off1] = e4m3x2(f11, f10);
        *(uint16_t*)&O8l[off0] = e4m3x2((f01 - h01) * 512.f, (f00 - h00) * 512.f);
        *(uint16_t*)&O8l[off1] = e4m3x2((f11 - h11) * 512.f, (f10 - h10) * 512.f);
    }
}

// ==================== launch ================================================
extern "C" void kernel_launch(void* const* d_in, const int* in_sizes, int n_in,
                              void* d_out, int out_size)
{
    (void)in_sizes; (void)n_in; (void)out_size;
    const float* x   = (const float*)d_in[0];
    const float* cf  = (const float*)d_in[1];
    const float* sf  = (const float*)d_in[2];
    const float* cki = (const float*)d_in[5];
    const float* cvi = (const float*)d_in[6];
    const float* wq  = (const float*)d_in[7];
    const float* wk  = (const float*)d_in[8];
    const float* wv  = (const float*)d_in[9];
    const float* wo  = (const float*)d_in[10];

    float* out    = (float*)d_out;
    float* out_ck = out + (size_t)SEQLEN * DIM;
    float* out_cv = out_ck + (size_t)WINDOW * KSTRIDE;

    __nv_bfloat16 *xh, *wh, *woh, *aoh, *qh, *ql, *kh, *kl, *vh, *vl;
    uint8_t *x8h, *x8l, *w8h, *w8l, *wo8h, *wo8l, *ao8h, *ao8l;
    cudaGetSymbolAddress((void**)&xh,   g_xh);
    cudaGetSymbolAddress((void**)&x8h,  g_x8h);
    cudaGetSymbolAddress((void**)&x8l,  g_x8l);
    cudaGetSymbolAddress((void**)&wh,   g_wh);
    cudaGetSymbolAddress((void**)&w8h,  g_w8h);
    cudaGetSymbolAddress((void**)&w8l,  g_w8l);
    cudaGetSymbolAddress((void**)&woh,  g_woh);
    cudaGetSymbolAddress((void**)&wo8h, g_wo8h);
    cudaGetSymbolAddress((void**)&wo8l, g_wo8l);
    cudaGetSymbolAddress((void**)&aoh,  g_aoh);
    cudaGetSymbolAddress((void**)&ao8h, g_ao8h);
    cudaGetSymbolAddress((void**)&ao8l, g_ao8l);
    cudaGetSymbolAddress((void**)&qh,   g_qh);
    cudaGetSymbolAddress((void**)&ql,   g_ql);
    cudaGetSymbolAddress((void**)&kh,   g_kh);
    cudaGetSymbolAddress((void**)&kl,   g_kl);
    cudaGetSymbolAddress((void**)&vh,   g_vh);
    cudaGetSymbolAddress((void**)&vl,   g_vl);

    cudaFuncSetAttribute(gemm_fused,
                         cudaFuncAttributeMaxDynamicSharedMemorySize, GSMEM_BYTES);
    cudaFuncSetAttribute(flash_mma,
                         cudaFuncAttributeMaxDynamicSharedMemorySize, ATT_SMEM);

    // merged splits
    split_all_kernel<<<(SPLIT_TOTAL + 255) / 256, 256>>>(
        x, wq, wk, wv, wo,
        xh, x8h, x8l, wh, w8h, w8l, woh, wo8h, wo8l);

    // fused QKV projection + rope + split + cache head
    gemm_fused<<<dim3(NQKV / 128, SEQLEN / 128), 256, GSMEM_BYTES>>>(
        xh, x8h, x8l, wh, w8h, w8l, nullptr, cf, sf,
        qh, ql, kh, kl, vh, vl, out_ck, out_cv, NQKV, DIM, 1);

    cache_tail_kernel<<<((WINDOW - SEQLEN) * KSTRIDE) / 256, 256>>>(cki, cvi, out_ck, out_cv);

    // flash attention
    flash_mma<<<dim3(SEQLEN / 128, NHEADS), 256, ATT_SMEM>>>(
        qh, ql, kh, kl, vh, vl, aoh, ao8h, ao8l);

    // output projection
    gemm_fused<<<dim3(DIM / 128, SEQLEN / 128), 256, GSMEM_BYTES>>>(
        aoh, ao8h, ao8l, woh, wo8h, wo8l, out, nullptr, nullptr,
        nullptr, nullptr, nullptr, nullptr, nullptr, nullptr,
        nullptr, nullptr, DIM, DIM, 0);
}

// round 12
// speedup vs baseline: 1.1651x; 1.1651x over previous
#include <cuda_runtime.h>
#include <cuda_bf16.h>
#include <cstdint>
#include <math.h>

#define SEQLEN   2048
#define DIM      4096
#define NHEADS   32
#define NKV      8
#define HD       128
#define WINDOW   4096
#define QSTRIDE  (NHEADS * HD)   // 4096
#define KSTRIDE  (NKV * HD)      // 1024
#define NQKV     (QSTRIDE + 2 * KSTRIDE)   // 6144
#define ATT_SCALE 0.08838834764831843f

// ==================== scratch ==============================================
__device__ __nv_bfloat16 g_xh [(size_t)SEQLEN * DIM];
__device__ __nv_bfloat16 g_xl [(size_t)SEQLEN * DIM];
__device__ __nv_bfloat16 g_wh [(size_t)NQKV * DIM];     // wq|wk|wv packed
__device__ __nv_bfloat16 g_wl [(size_t)NQKV * DIM];
__device__ __nv_bfloat16 g_woh[(size_t)DIM * QSTRIDE];
__device__ __nv_bfloat16 g_wol[(size_t)DIM * QSTRIDE];
__device__ __nv_bfloat16 g_aoh[(size_t)SEQLEN * QSTRIDE];
__device__ __nv_bfloat16 g_aol[(size_t)SEQLEN * QSTRIDE];
__device__ __nv_bfloat16 g_qh[(size_t)SEQLEN * QSTRIDE];
__device__ __nv_bfloat16 g_ql[(size_t)SEQLEN * QSTRIDE];
__device__ __nv_bfloat16 g_kh[(size_t)SEQLEN * KSTRIDE];
__device__ __nv_bfloat16 g_kl[(size_t)SEQLEN * KSTRIDE];
__device__ __nv_bfloat16 g_vh[(size_t)SEQLEN * KSTRIDE];
__device__ __nv_bfloat16 g_vl[(size_t)SEQLEN * KSTRIDE];

// ==================== helpers ===============================================
__device__ __forceinline__ void mma16816(float* c, const uint32_t* a,
                                         uint32_t b0, uint32_t b1) {
    asm volatile(
        "mma.sync.aligned.m16n8k16.row.col.f32.bf16.bf16.f32 "
        "{%0,%1,%2,%3}, {%4,%5,%6,%7}, {%8,%9}, {%0,%1,%2,%3};"
        : "+f"(c[0]), "+f"(c[1]), "+f"(c[2]), "+f"(c[3])
        : "r"(a[0]), "r"(a[1]), "r"(a[2]), "r"(a[3]), "r"(b0), "r"(b1));
}
__device__ __forceinline__ void cp_async16(void* smem_dst, const void* gmem_src) {
    uint32_t sa;
    asm("{ .reg .u64 t; cvta.to.shared.u64 t, %1; cvt.u32.u64 %0, t; }"
        : "=r"(sa) : "l"(smem_dst));
    asm volatile("cp.async.cg.shared.global [%0], [%1], 16;" :: "r"(sa), "l"(gmem_src));
}
#define CP_COMMIT() asm volatile("cp.async.commit_group;" ::: "memory")
__device__ __forceinline__ void ldsm_x4(uint32_t* r, uint32_t addr) {
    asm volatile("ldmatrix.sync.aligned.m8n8.x4.shared.b16 {%0,%1,%2,%3}, [%4];"
        : "=r"(r[0]), "=r"(r[1]), "=r"(r[2]), "=r"(r[3]) : "r"(addr));
}
__device__ __forceinline__ void ldsm_x4_t(uint32_t* r, uint32_t addr) {
    asm volatile("ldmatrix.sync.aligned.m8n8.x4.trans.shared.b16 {%0,%1,%2,%3}, [%4];"
        : "=r"(r[0]), "=r"(r[1]), "=r"(r[2]), "=r"(r[3]) : "r"(addr));
}
__device__ __forceinline__ uint32_t smem_u32(const void* p) {
    uint32_t a;
    asm("{ .reg .u64 t; cvta.to.shared.u64 t, %1; cvt.u32.u64 %0, t; }"
        : "=r"(a) : "l"(p));
    return a;
}
__device__ __forceinline__ uint32_t pack2(float a, float b) {
    __nv_bfloat162 t = __floats2bfloat162_rn(a, b);
    return *(uint32_t*)&t;
}
__device__ __forceinline__ void store_hilo(__nv_bfloat16* H, __nv_bfloat16* L,
                                           size_t off, float a, float b) {
    float ha = __bfloat162float(__float2bfloat16_rn(a));
    float hb = __bfloat162float(__float2bfloat16_rn(b));
    *(uint32_t*)&H[off] = pack2(ha, hb);
    *(uint32_t*)&L[off] = pack2(a - ha, b - hb);
}

// ==================== merged fp32 -> bf16 hi/lo split (all tensors) =========
#define SPLIT_R0 1048576u                     // x
#define SPLIT_R1 (SPLIT_R0 + 2097152u)        // wq
#define SPLIT_R2 (SPLIT_R1 + 524288u)         // wk
#define SPLIT_R3 (SPLIT_R2 + 524288u)         // wv
#define SPLIT_R4 (SPLIT_R3 + 2097152u)        // wo
#define SPLIT_TOTAL SPLIT_R4

__global__ void split_all_kernel(const float* __restrict__ x,
                                 const float* __restrict__ wq,
                                 const float* __restrict__ wk,
                                 const float* __restrict__ wv,
                                 const float* __restrict__ wo,
                                 __nv_bfloat16* __restrict__ xh, __nv_bfloat16* __restrict__ xl,
                                 __nv_bfloat16* __restrict__ wh, __nv_bfloat16* __restrict__ wl,
                                 __nv_bfloat16* __restrict__ woh, __nv_bfloat16* __restrict__ wol)
{
    uint32_t i = blockIdx.x * blockDim.x + threadIdx.x;
    if (i >= SPLIT_TOTAL) return;

    const float* src;
    __nv_bfloat16 *hi, *lo;
    uint32_t j;
    if (i < SPLIT_R0)      { src = x;  hi = xh;  lo = xl;  j = i; }
    else if (i < SPLIT_R1) { src = wq; hi = wh;  lo = wl;  j = i - SPLIT_R0; }
    else if (i < SPLIT_R2) { src = wk; hi = wh + (size_t)QSTRIDE * DIM;
                             lo = wl + (size_t)QSTRIDE * DIM; j = i - SPLIT_R1; }
    else if (i < SPLIT_R3) { src = wv; hi = wh + (size_t)(QSTRIDE + KSTRIDE) * DIM;
                             lo = wl + (size_t)(QSTRIDE + KSTRIDE) * DIM; j = i - SPLIT_R2; }
    else                   { src = wo; hi = woh; lo = wol; j = i - SPLIT_R3; }

    float4 v0 = ((const float4*)src)[2 * (size_t)j];
    float4 v1 = ((const float4*)src)[2 * (size_t)j + 1];
    float f[8] = { v0.x, v0.y, v0.z, v0.w, v1.x, v1.y, v1.z, v1.w };
    uint32_t hw[4], lw[4];
#pragma unroll
    for (int k = 0; k < 4; k++) {
        float h0 = __bfloat162float(__float2bfloat16_rn(f[2 * k]));
        float h1 = __bfloat162float(__float2bfloat16_rn(f[2 * k + 1]));
        hw[k] = pack2(h0, h1);
        lw[k] = pack2(f[2 * k] - h0, f[2 * k + 1] - h1);
    }
    ((uint4*)hi)[j] = make_uint4(hw[0], hw[1], hw[2], hw[3]);
    ((uint4*)lo)[j] = make_uint4(lw[0], lw[1], lw[2], lw[3]);
}

// ==================== HMMA bf16x3 GEMM (ldmatrix mainloop, occ 2) ===========
#define GPAD     40
#define SUBT_B   (128 * GPAD * 2)
#define STAGE_B  (4 * SUBT_B)
#define GSMEM_BYTES (2 * STAGE_B)

__global__ __launch_bounds__(256, 2) void gemm_fused(
    const __nv_bfloat16* __restrict__ Ah, const __nv_bfloat16* __restrict__ Al,
    const __nv_bfloat16* __restrict__ Bh, const __nv_bfloat16* __restrict__ Bl,
    float* __restrict__ C,
    const float* __restrict__ cf, const float* __restrict__ sf,
    __nv_bfloat16* __restrict__ Qh, __nv_bfloat16* __restrict__ Ql,
    __nv_bfloat16* __restrict__ Kh, __nv_bfloat16* __restrict__ Kl,
    __nv_bfloat16* __restrict__ Vh, __nv_bfloat16* __restrict__ Vl,
    float* __restrict__ CK, float* __restrict__ CV,
    int N, int K, int mode)
{
    extern __shared__ char sm[];
    const int tid  = threadIdx.x;
    const int wid  = tid >> 5;
    const int lane = tid & 31;
    const int g    = lane >> 2;
    const int tg   = lane & 3;
    const int wm   = wid & 1;
    const int wn   = wid >> 1;
    const int bm   = blockIdx.y << 7;
    const int bn   = blockIdx.x << 7;

    const __nv_bfloat16* gsrc[4] = { Ah, Al, Bh, Bl };
    const int row0[4] = { bm, bm, bn, bn };

    auto load_stage = [&](int s, int k0) {
        char* base = sm + s * STAGE_B;
#pragma unroll
        for (int t = 0; t < 8; t++) {
            int id  = tid + (t << 8);
            int sub = id >> 9;
            int idx = id & 511;
            int r   = idx >> 2;
            int c   = idx & 3;
            char* dst = base + sub * SUBT_B + r * (GPAD * 2) + c * 16;
            const __nv_bfloat16* src =
                gsrc[sub] + (size_t)(row0[sub] + r) * K + k0 + c * 8;
            cp_async16(dst, src);
        }
        CP_COMMIT();
    };

    float acc[4][4][4];
#pragma unroll
    for (int m = 0; m < 4; m++)
#pragma unroll
        for (int n = 0; n < 4; n++)
#pragma unroll
            for (int k = 0; k < 4; k++) acc[m][n][k] = 0.f;

    const uint32_t sbase = smem_u32(sm);
    const uint32_t lrow = lane & 15;
    const uint32_t lcol = (lane >> 4) << 3;
    const uint32_t a_off = ((wm * 64 + lrow) * GPAD + lcol) * 2;
    const uint32_t b_off = ((wn * 32 + lrow) * GPAD + lcol) * 2;

    const int NIT = K >> 5;
    load_stage(0, 0);

    for (int it = 0; it < NIT; it++) {
        asm volatile("cp.async.wait_group 0;" ::: "memory");
        __syncthreads();
        if (it + 1 < NIT) load_stage((it + 1) & 1, (it + 1) << 5);

        const uint32_t st = sbase + (it & 1) * STAGE_B;
        const uint32_t aH = st + a_off;
        const uint32_t aL = aH + SUBT_B;
        const uint32_t bH = st + 2 * SUBT_B + b_off;
        const uint32_t bL = bH + SUBT_B;

#pragma unroll
        for (int ks2 = 0; ks2 < 2; ks2++) {
            const uint32_t kso = ks2 * 32;
            uint32_t rbh[2][4], rbl[2][4];
            ldsm_x4(rbh[0], bH + kso);
            ldsm_x4(rbh[1], bH + 16 * GPAD * 2 + kso);
            ldsm_x4(rbl[0], bL + kso);
            ldsm_x4(rbl[1], bL + 16 * GPAD * 2 + kso);
#pragma unroll
            for (int m = 0; m < 4; m++) {
                uint32_t rah[4], ral[4];
                ldsm_x4(rah, aH + m * 16 * GPAD * 2 + kso);
                ldsm_x4(ral, aL + m * 16 * GPAD * 2 + kso);
#pragma unroll
                for (int p = 0; p < 2; p++) {
                    mma16816(acc[m][2 * p],     rah, rbh[p][0], rbh[p][2]);
                    mma16816(acc[m][2 * p],     rah, rbl[p][0], rbl[p][2]);
                    mma16816(acc[m][2 * p],     ral, rbh[p][0], rbh[p][2]);
                    mma16816(acc[m][2 * p + 1], rah, rbh[p][1], rbh[p][3]);
                    mma16816(acc[m][2 * p + 1], rah, rbl[p][1], rbl[p][3]);
                    mma16816(acc[m][2 * p + 1], ral, rbh[p][1], rbh[p][3]);
                }
            }
        }
        __syncthreads();
    }

    if (mode == 0) {
#pragma unroll
        for (int m = 0; m < 4; m++) {
            int r0 = bm + wm * 64 + m * 16 + g;
#pragma unroll
            for (int n = 0; n < 4; n++) {
                int col = bn + wn * 32 + n * 8 + 2 * tg;
                *(float2*)&C[(size_t)r0 * N + col] =
                    make_float2(acc[m][n][0], acc[m][n][1]);
                *(float2*)&C[(size_t)(r0 + 8) * N + col] =
                    make_float2(acc[m][n][2], acc[m][n][3]);
            }
        }
    } else if (bn < QSTRIDE) {
        // ---- Q region: rope + scale + hi/lo split ----
#pragma unroll
        for (int m = 0; m < 4; m++) {
            int r0 = bm + wm * 64 + m * 16 + g;
#pragma unroll
            for (int n = 0; n < 4; n++) {
                int col = bn + wn * 32 + n * 8 + 2 * tg;
                int d = (col & 127) >> 1;
                float cA = cf[r0 * 64 + d], sA = sf[r0 * 64 + d];
                float u0 = (acc[m][n][0] * cA - acc[m][n][1] * sA) * ATT_SCALE;
                float v0 = (acc[m][n][0] * sA + acc[m][n][1] * cA) * ATT_SCALE;
                store_hilo(Qh, Ql, (size_t)r0 * QSTRIDE + col, u0, v0);
                float cB = cf[(r0 + 8) * 64 + d], sB = sf[(r0 + 8) * 64 + d];
                float u1 = (acc[m][n][2] * cB - acc[m][n][3] * sB) * ATT_SCALE;
                float v1 = (acc[m][n][2] * sB + acc[m][n][3] * cB) * ATT_SCALE;
                store_hilo(Qh, Ql, (size_t)(r0 + 8) * QSTRIDE + col, u1, v1);
            }
        }
    } else if (bn < QSTRIDE + KSTRIDE) {
        // ---- K region: rope + cache + hi/lo split ----
#pragma unroll
        for (int m = 0; m < 4; m++) {
            int r0 = bm + wm * 64 + m * 16 + g;
#pragma unroll
            for (int n = 0; n < 4; n++) {
                int colk = bn - QSTRIDE + wn * 32 + n * 8 + 2 * tg;
                int d = (colk & 127) >> 1;
                float cA = cf[r0 * 64 + d], sA = sf[r0 * 64 + d];
                float u0 = acc[m][n][0] * cA - acc[m][n][1] * sA;
                float v0 = acc[m][n][0] * sA + acc[m][n][1] * cA;
                *(float2*)&CK[(size_t)r0 * KSTRIDE + colk] = make_float2(u0, v0);
                store_hilo(Kh, Kl, (size_t)r0 * KSTRIDE + colk, u0, v0);
                float cB = cf[(r0 + 8) * 64 + d], sB = sf[(r0 + 8) * 64 + d];
                float u1 = acc[m][n][2] * cB - acc[m][n][3] * sB;
                float v1 = acc[m][n][2] * sB + acc[m][n][3] * cB;
                *(float2*)&CK[(size_t)(r0 + 8) * KSTRIDE + colk] = make_float2(u1, v1);
                store_hilo(Kh, Kl, (size_t)(r0 + 8) * KSTRIDE + colk, u1, v1);
            }
        }
    } else {
        // ---- V region: cache + hi/lo split ----
#pragma unroll
        for (int m = 0; m < 4; m++) {
            int r0 = bm + wm * 64 + m * 16 + g;
#pragma unroll
            for (int n = 0; n < 4; n++) {
                int colv = bn - QSTRIDE - KSTRIDE + wn * 32 + n * 8 + 2 * tg;
                *(float2*)&CV[(size_t)r0 * KSTRIDE + colv] =
                    make_float2(acc[m][n][0], acc[m][n][1]);
                store_hilo(Vh, Vl, (size_t)r0 * KSTRIDE + colv,
                           acc[m][n][0], acc[m][n][1]);
                *(float2*)&CV[(size_t)(r0 + 8) * KSTRIDE + colv] =
                    make_float2(acc[m][n][2], acc[m][n][3]);
                store_hilo(Vh, Vl, (size_t)(r0 + 8) * KSTRIDE + colv,
                           acc[m][n][2], acc[m][n][3]);
            }
        }
    }
}

// ==================== cache tail ============================================
__global__ void cache_tail_kernel(const float* __restrict__ cki,
                                  const float* __restrict__ cvi,
                                  float* __restrict__ cko,
                                  float* __restrict__ cvo)
{
    int idx = blockIdx.x * blockDim.x + threadIdx.x;
    if (idx >= (WINDOW - SEQLEN) * KSTRIDE) return;
    size_t off = (size_t)SEQLEN * KSTRIDE + idx;
    cko[off] = cki[off];
    cvo[off] = cvi[off];
}

// ==================== HMMA flash attention (R6/R10-proven version) ==========
#define SPAD      136
#define Q_ELEMS   (128 * SPAD)
#define KV_ELEMS  (64 * SPAD)
#define ATT_SMEM  ((2 * Q_ELEMS + 8 * KV_ELEMS) * 2)

__global__ __launch_bounds__(256, 1) void flash_mma(
    const __nv_bfloat16* __restrict__ Qhg, const __nv_bfloat16* __restrict__ Qlg,
    const __nv_bfloat16* __restrict__ Khg, const __nv_bfloat16* __restrict__ Klg,
    const __nv_bfloat16* __restrict__ Vhg, const __nv_bfloat16* __restrict__ Vlg,
    __nv_bfloat16* __restrict__ Ohg, __nv_bfloat16* __restrict__ Olg)
{
    extern __shared__ __nv_bfloat16 sb[];
    const int tid  = threadIdx.x;
    const int wid  = tid >> 5;
    const int lane = tid & 31;
    const int g    = lane >> 2;
    const int tg   = lane & 3;
    const int qb   = (int)(gridDim.x - 1 - blockIdx.x);
    const int h    = blockIdx.y;
    const int kvh  = h >> 2;
    const int q0   = qb << 7;
    const int mr   = wid << 4;

    __nv_bfloat16* Qhs = sb;
    __nv_bfloat16* Qls = sb + Q_ELEMS;
    __nv_bfloat16* KVs = sb + 2 * Q_ELEMS;
    const uint32_t sbase = smem_u32(sb);

    {
        const __nv_bfloat16* gq[2] = { Qhg, Qlg };
#pragma unroll
        for (int i = 0; i < 16; i++) {
            int id  = tid + (i << 8);
            int tsr = id >> 11, idx = id & 2047;
            int r = idx >> 4, c = idx & 15;
            cp_async16(sb + tsr * Q_ELEMS + r * SPAD + c * 8,
                       gq[tsr] + (size_t)(q0 + r) * QSTRIDE + h * HD + c * 8);
        }
        CP_COMMIT();
    }

    const int NT = 2 * qb + 2;
    const __nv_bfloat16* gkv[4] = { Khg, Klg, Vhg, Vlg };
    auto load_kv = [&](int t, int st) {
        __nv_bfloat16* base = KVs + st * 4 * KV_ELEMS;
#pragma unroll
        for (int i = 0; i < 16; i++) {
            int id  = tid + (i << 8);
            int sub = id >> 10, idx = id & 1023;
            int r = idx >> 4, c = idx & 15;
            cp_async16(base + sub * KV_ELEMS + r * SPAD + c * 8,
                       gkv[sub] + (size_t)(t * 64 + r) * KSTRIDE + kvh * HD + c * 8);
        }
        CP_COMMIT();
    };
    load_kv(0, 0);

    float m0 = -1e30f, m1 = -1e30f, l0 = 0.f, l1 = 0.f;
    float o[16][4];
#pragma unroll
    for (int n = 0; n < 16; n++)
#pragma unroll
        for (int c = 0; c < 4; c++) o[n][c] = 0.f;

    for (int t = 0; t < NT; t++) {
        if (t + 1 < NT) {
            load_kv(t + 1, (t + 1) & 1);
            asm volatile("cp.async.wait_group 1;" ::: "memory");
        } else {
            asm volatile("cp.async.wait_group 0;" ::: "memory");
        }
        __syncthreads();

        if (t * 64 <= q0 + mr + 15) {
            const __nv_bfloat16* Khs = KVs + (t & 1) * 4 * KV_ELEMS;
            const __nv_bfloat16* Kls = Khs + KV_ELEMS;
            const uint32_t vh_base = sbase +
                (uint32_t)(2 * Q_ELEMS + (t & 1) * 4 * KV_ELEMS + 2 * KV_ELEMS) * 2;
            const uint32_t vl_base = vh_base + KV_ELEMS * 2;

            float sc[8][4];
#pragma unroll
            for (int n = 0; n < 8; n++)
#pragma unroll
                for (int c = 0; c < 4; c++) sc[n][c] = 0.f;

#pragma unroll
            for (int k = 0; k < 8; k++) {
                int ks = k << 4;
                uint32_t qh[4], ql[4];
                qh[0] = *(const uint32_t*)&Qhs[(mr + g)     * SPAD + ks + 2 * tg];
                qh[1] = *(const uint32_t*)&Qhs[(mr + 8 + g) * SPAD + ks + 2 * tg];
                qh[2] = *(const uint32_t*)&Qhs[(mr + g)     * SPAD + ks + 8 + 2 * tg];
                qh[3] = *(const uint32_t*)&Qhs[(mr + 8 + g) * SPAD + ks + 8 + 2 * tg];
                ql[0] = *(const uint32_t*)&Qls[(mr + g)     * SPAD + ks + 2 * tg];
                ql[1] = *(const uint32_t*)&Qls[(mr + 8 + g) * SPAD + ks + 2 * tg];
                ql[2] = *(const uint32_t*)&Qls[(mr + g)     * SPAD + ks + 8 + 2 * tg];
                ql[3] = *(const uint32_t*)&Qls[(mr + 8 + g) * SPAD + ks + 8 + 2 * tg];
#pragma unroll
                for (int n = 0; n < 8; n++) {
                    uint32_t kh0, kh1, kl0, kl1;
                    kh0 = *(const uint32_t*)&Khs[(8 * n + g) * SPAD + ks + 2 * tg];
                    kh1 = *(const uint32_t*)&Khs[(8 * n + g) * SPAD + ks + 8 + 2 * tg];
                    kl0 = *(const uint32_t*)&Kls[(8 * n + g) * SPAD + ks + 2 * tg];
                    kl1 = *(const uint32_t*)&Kls[(8 * n + g) * SPAD + ks + 8 + 2 * tg];
                    mma16816(sc[n], qh, kh0, kh1);
                    mma16816(sc[n], qh, kl0, kl1);
                    mma16816(sc[n], ql, kh0, kh1);
                }
            }

            const int qi0 = q0 + mr + g, qi1 = qi0 + 8;
            if (t * 64 + 63 > q0 + mr) {
#pragma unroll
                for (int n = 0; n < 8; n++) {
                    int kj = t * 64 + 8 * n + 2 * tg;
                    if (kj     > qi0) sc[n][0] = -1e30f;
                    if (kj + 1 > qi0) sc[n][1] = -1e30f;
                    if (kj     > qi1) sc[n][2] = -1e30f;
                    if (kj + 1 > qi1) sc[n][3] = -1e30f;
                }
            }

            float mt0 = -1e30f, mt1 = -1e30f;
#pragma unroll
            for (int n = 0; n < 8; n++) {
                mt0 = fmaxf(mt0, fmaxf(sc[n][0], sc[n][1]));
                mt1 = fmaxf(mt1, fmaxf(sc[n][2], sc[n][3]));
            }
            mt0 = fmaxf(mt0, __shfl_xor_sync(0xffffffffu, mt0, 1));
            mt0 = fmaxf(mt0, __shfl_xor_sync(0xffffffffu, mt0, 2));
            mt1 = fmaxf(mt1, __shfl_xor_sync(0xffffffffu, mt1, 1));
            mt1 = fmaxf(mt1, __shfl_xor_sync(0xffffffffu, mt1, 2));
            float m0n = fmaxf(m0, mt0), m1n = fmaxf(m1, mt1);
            float c0 = __expf(m0 - m0n), c1 = __expf(m1 - m1n);
            float rs0 = 0.f, rs1 = 0.f;
#pragma unroll
            for (int n = 0; n < 8; n++) {
                sc[n][0] = __expf(sc[n][0] - m0n);
                sc[n][1] = __expf(sc[n][1] - m0n);
                sc[n][2] = __expf(sc[n][2] - m1n);
                sc[n][3] = __expf(sc[n][3] - m1n);
                rs0 += sc[n][0] + sc[n][1];
                rs1 += sc[n][2] + sc[n][3];
            }
            rs0 += __shfl_xor_sync(0xffffffffu, rs0, 1);
            rs0 += __shfl_xor_sync(0xffffffffu, rs0, 2);
            rs1 += __shfl_xor_sync(0xffffffffu, rs1, 1);
            rs1 += __shfl_xor_sync(0xffffffffu, rs1, 2);
            l0 = l0 * c0 + rs0;
            l1 = l1 * c1 + rs1;
            m0 = m0n; m1 = m1n;
#pragma unroll
            for (int n = 0; n < 16; n++) {
                o[n][0] *= c0; o[n][1] *= c0; o[n][2] *= c1; o[n][3] *= c1;
            }

            uint32_t ph[4][4], pl[4][4];
#pragma unroll
            for (int j = 0; j < 4; j++) {
                const float* A = sc[2 * j];
                const float* B = sc[2 * j + 1];
                float ah0 = __bfloat162float(__float2bfloat16_rn(A[0]));
                float ah1 = __bfloat162float(__float2bfloat16_rn(A[1]));
                float ah2 = __bfloat162float(__float2bfloat16_rn(A[2]));
                float ah3 = __bfloat162float(__float2bfloat16_rn(A[3]));
                float bh0 = __bfloat162float(__float2bfloat16_rn(B[0]));
                float bh1 = __bfloat162float(__float2bfloat16_rn(B[1]));
                float bh2 = __bfloat162float(__float2bfloat16_rn(B[2]));
                float bh3 = __bfloat162float(__float2bfloat16_rn(B[3]));
                ph[j][0] = pack2(ah0, ah1);
                ph[j][1] = pack2(ah2, ah3);
                ph[j][2] = pack2(bh0, bh1);
                ph[j][3] = pack2(bh2, bh3);
                pl[j][0] = pack2(A[0] - ah0, A[1] - ah1);
                pl[j][1] = pack2(A[2] - ah2, A[3] - ah3);
                pl[j][2] = pack2(B[0] - bh0, B[1] - bh1);
                pl[j][3] = pack2(B[2] - bh2, B[3] - bh3);
            }

            const uint32_t va = (uint32_t)(((lane & 15) * SPAD + ((lane >> 4) << 3)) * 2);
#pragma unroll
            for (int j = 0; j < 4; j++) {
                const uint32_t kvoff = va + (uint32_t)(16 * j * SPAD * 2);
#pragma unroll
                for (int u = 0; u < 8; u++) {
                    uint32_t vh[4], vl[4];
                    ldsm_x4_t(vh, vh_base + kvoff + u * 32);
                    ldsm_x4_t(vl, vl_base + kvoff + u * 32);
                    mma16816(o[2 * u],     ph[j], vh[0], vh[1]);
                    mma16816(o[2 * u],     ph[j], vl[0], vl[1]);
                    mma16816(o[2 * u],     pl[j], vh[0], vh[1]);
                    mma16816(o[2 * u + 1], ph[j], vh[2], vh[3]);
                    mma16816(o[2 * u + 1], ph[j], vl[2], vl[3]);
                    mma16816(o[2 * u + 1], pl[j], vh[2], vh[3]);
                }
            }
        }
        __syncthreads();
    }

    const float inv0 = 1.f / l0, inv1 = 1.f / l1;
    const int row0 = q0 + mr + g, row1 = row0 + 8;
#pragma unroll
    for (int n = 0; n < 16; n++) {
        int col = h * HD + 8 * n + 2 * tg;
        float f00 = o[n][0] * inv0, f01 = o[n][1] * inv0;
        float f10 = o[n][2] * inv1, f11 = o[n][3] * inv1;
        store_hilo(Ohg, Olg, (size_t)row0 * QSTRIDE + col, f00, f01);
        store_hilo(Ohg, Olg, (size_t)row1 * QSTRIDE + col, f10, f11);
    }
}

// ==================== launch ================================================
extern "C" void kernel_launch(void* const* d_in, const int* in_sizes, int n_in,
                              void* d_out, int out_size)
{
    (void)in_sizes; (void)n_in; (void)out_size;
    const float* x   = (const float*)d_in[0];
    const float* cf  = (const float*)d_in[1];
    const float* sf  = (const float*)d_in[2];
    const float* cki = (const float*)d_in[5];
    const float* cvi = (const float*)d_in[6];
    const float* wq  = (const float*)d_in[7];
    const float* wk  = (const float*)d_in[8];
    const float* wv  = (const float*)d_in[9];
    const float* wo  = (const float*)d_in[10];

    float* out    = (float*)d_out;
    float* out_ck = out + (size_t)SEQLEN * DIM;
    float* out_cv = out_ck + (size_t)WINDOW * KSTRIDE;

    __nv_bfloat16 *xh, *xl, *wh, *wl, *woh, *wol, *aoh, *aol;
    __nv_bfloat16 *qh, *ql, *kh, *kl, *vh, *vl;
    cudaGetSymbolAddress((void**)&xh,  g_xh);
    cudaGetSymbolAddress((void**)&xl,  g_xl);
    cudaGetSymbolAddress((void**)&wh,  g_wh);
    cudaGetSymbolAddress((void**)&wl,  g_wl);
    cudaGetSymbolAddress((void**)&woh, g_woh);
    cudaGetSymbolAddress((void**)&wol, g_wol);
    cudaGetSymbolAddress((void**)&aoh, g_aoh);
    cudaGetSymbolAddress((void**)&aol, g_aol);
    cudaGetSymbolAddress((void**)&qh,  g_qh);
    cudaGetSymbolAddress((void**)&ql,  g_ql);
    cudaGetSymbolAddress((void**)&kh,  g_kh);
    cudaGetSymbolAddress((void**)&kl,  g_kl);
    cudaGetSymbolAddress((void**)&vh,  g_vh);
    cudaGetSymbolAddress((void**)&vl,  g_vl);

    cudaFuncSetAttribute(gemm_fused,
                         cudaFuncAttributeMaxDynamicSharedMemorySize, GSMEM_BYTES);
    cudaFuncSetAttribute(flash_mma,
                         cudaFuncAttributeMaxDynamicSharedMemorySize, ATT_SMEM);

    // merged splits: x, wq|wk|wv (packed), wo
    split_all_kernel<<<(SPLIT_TOTAL + 255) / 256, 256>>>(
        x, wq, wk, wv, wo, xh, xl, wh, wl, woh, wol);

    // fused QKV projection + rope + split + cache head
    gemm_fused<<<dim3(NQKV / 128, SEQLEN / 128), 256, GSMEM_BYTES>>>(
        xh, xl, wh, wl, nullptr, cf, sf,
        qh, ql, kh, kl, vh, vl, out_ck, out_cv, NQKV, DIM, 1);

    cache_tail_kernel<<<((WINDOW - SEQLEN) * KSTRIDE) / 256, 256>>>(cki, cvi, out_ck, out_cv);

    // flash attention (R10-proven)
    flash_mma<<<dim3(SEQLEN / 128, NHEADS), 256, ATT_SMEM>>>(qh, ql, kh, kl, vh, vl, aoh, aol);

    // output projection
    gemm_fused<<<dim3(DIM / 128, SEQLEN / 128), 256, GSMEM_BYTES>>>(
        aoh, aol, woh, wol, out, nullptr, nullptr,
        nullptr, nullptr, nullptr, nullptr, nullptr, nullptr,
        nullptr, nullptr, DIM, DIM, 0);
}

// round 13
// speedup vs baseline: 1.2828x; 1.1011x over previous
#include <cuda_runtime.h>
#include <cuda_bf16.h>
#include <cstdint>
#include <math.h>

#define SEQLEN   2048
#define DIM      4096
#define NHEADS   32
#define NKV      8
#define HD       128
#define WINDOW   4096
#define QSTRIDE  (NHEADS * HD)   // 4096
#define KSTRIDE  (NKV * HD)      // 1024
#define NQKV     (QSTRIDE + 2 * KSTRIDE)   // 6144
#define ATT_SCALE 0.08838834764831843f

// ==================== scratch ==============================================
__device__ __nv_bfloat16 g_xh [(size_t)SEQLEN * DIM];
__device__ __nv_bfloat16 g_xl [(size_t)SEQLEN * DIM];
__device__ __nv_bfloat16 g_wh [(size_t)NQKV * DIM];     // wq|wk|wv packed
__device__ __nv_bfloat16 g_wl [(size_t)NQKV * DIM];
__device__ __nv_bfloat16 g_woh[(size_t)DIM * QSTRIDE];
__device__ __nv_bfloat16 g_wol[(size_t)DIM * QSTRIDE];
__device__ __nv_bfloat16 g_aoh[(size_t)SEQLEN * QSTRIDE];
__device__ __nv_bfloat16 g_aol[(size_t)SEQLEN * QSTRIDE];
__device__ __nv_bfloat16 g_qh[(size_t)SEQLEN * QSTRIDE];
__device__ __nv_bfloat16 g_ql[(size_t)SEQLEN * QSTRIDE];
__device__ __nv_bfloat16 g_kh[(size_t)SEQLEN * KSTRIDE];
__device__ __nv_bfloat16 g_kl[(size_t)SEQLEN * KSTRIDE];
__device__ __nv_bfloat16 g_vh[(size_t)SEQLEN * KSTRIDE];
__device__ __nv_bfloat16 g_vl[(size_t)SEQLEN * KSTRIDE];

// ==================== helpers ===============================================
__device__ __forceinline__ void mma16816(float* c, const uint32_t* a,
                                         uint32_t b0, uint32_t b1) {
    asm volatile(
        "mma.sync.aligned.m16n8k16.row.col.f32.bf16.bf16.f32 "
        "{%0,%1,%2,%3}, {%4,%5,%6,%7}, {%8,%9}, {%0,%1,%2,%3};"
        : "+f"(c[0]), "+f"(c[1]), "+f"(c[2]), "+f"(c[3])
        : "r"(a[0]), "r"(a[1]), "r"(a[2]), "r"(a[3]), "r"(b0), "r"(b1));
}
__device__ __forceinline__ void cp_async16(void* smem_dst, const void* gmem_src) {
    uint32_t sa;
    asm("{ .reg .u64 t; cvta.to.shared.u64 t, %1; cvt.u32.u64 %0, t; }"
        : "=r"(sa) : "l"(smem_dst));
    asm volatile("cp.async.cg.shared.global [%0], [%1], 16;" :: "r"(sa), "l"(gmem_src));
}
#define CP_COMMIT() asm volatile("cp.async.commit_group;" ::: "memory")
__device__ __forceinline__ void ldsm_x4_t(uint32_t* r, uint32_t addr) {
    asm volatile("ldmatrix.sync.aligned.m8n8.x4.trans.shared.b16 {%0,%1,%2,%3}, [%4];"
        : "=r"(r[0]), "=r"(r[1]), "=r"(r[2]), "=r"(r[3]) : "r"(addr));
}
__device__ __forceinline__ uint32_t smem_u32(const void* p) {
    uint32_t a;
    asm("{ .reg .u64 t; cvta.to.shared.u64 t, %1; cvt.u32.u64 %0, t; }"
        : "=r"(a) : "l"(p));
    return a;
}
__device__ __forceinline__ uint32_t pack2(float a, float b) {
    __nv_bfloat162 t = __floats2bfloat162_rn(a, b);
    return *(uint32_t*)&t;
}
__device__ __forceinline__ void store_hilo(__nv_bfloat16* H, __nv_bfloat16* L,
                                           size_t off, float a, float b) {
    float ha = __bfloat162float(__float2bfloat16_rn(a));
    float hb = __bfloat162float(__float2bfloat16_rn(b));
    *(uint32_t*)&H[off] = pack2(ha, hb);
    *(uint32_t*)&L[off] = pack2(a - ha, b - hb);
}

// ==================== merged fp32 -> bf16 hi/lo split (all tensors) =========
#define SPLIT_R0 1048576u                     // x
#define SPLIT_R1 (SPLIT_R0 + 2097152u)        // wq
#define SPLIT_R2 (SPLIT_R1 + 524288u)         // wk
#define SPLIT_R3 (SPLIT_R2 + 524288u)         // wv
#define SPLIT_R4 (SPLIT_R3 + 2097152u)        // wo
#define SPLIT_TOTAL SPLIT_R4

__global__ void split_all_kernel(const float* __restrict__ x,
                                 const float* __restrict__ wq,
                                 const float* __restrict__ wk,
                                 const float* __restrict__ wv,
                                 const float* __restrict__ wo,
                                 __nv_bfloat16* __restrict__ xh, __nv_bfloat16* __restrict__ xl,
                                 __nv_bfloat16* __restrict__ wh, __nv_bfloat16* __restrict__ wl,
                                 __nv_bfloat16* __restrict__ woh, __nv_bfloat16* __restrict__ wol)
{
    uint32_t i = blockIdx.x * blockDim.x + threadIdx.x;
    if (i >= SPLIT_TOTAL) return;

    const float* src;
    __nv_bfloat16 *hi, *lo;
    uint32_t j;
    if (i < SPLIT_R0)      { src = x;  hi = xh;  lo = xl;  j = i; }
    else if (i < SPLIT_R1) { src = wq; hi = wh;  lo = wl;  j = i - SPLIT_R0; }
    else if (i < SPLIT_R2) { src = wk; hi = wh + (size_t)QSTRIDE * DIM;
                             lo = wl + (size_t)QSTRIDE * DIM; j = i - SPLIT_R1; }
    else if (i < SPLIT_R3) { src = wv; hi = wh + (size_t)(QSTRIDE + KSTRIDE) * DIM;
                             lo = wl + (size_t)(QSTRIDE + KSTRIDE) * DIM; j = i - SPLIT_R2; }
    else                   { src = wo; hi = woh; lo = wol; j = i - SPLIT_R3; }

    float4 v0 = ((const float4*)src)[2 * (size_t)j];
    float4 v1 = ((const float4*)src)[2 * (size_t)j + 1];
    float f[8] = { v0.x, v0.y, v0.z, v0.w, v1.x, v1.y, v1.z, v1.w };
    uint32_t hw[4], lw[4];
#pragma unroll
    for (int k = 0; k < 4; k++) {
        float h0 = __bfloat162float(__float2bfloat16_rn(f[2 * k]));
        float h1 = __bfloat162float(__float2bfloat16_rn(f[2 * k + 1]));
        hw[k] = pack2(h0, h1);
        lw[k] = pack2(f[2 * k] - h0, f[2 * k + 1] - h1);
    }
    ((uint4*)hi)[j] = make_uint4(hw[0], hw[1], hw[2], hw[3]);
    ((uint4*)lo)[j] = make_uint4(lw[0], lw[1], lw[2], lw[3]);
}

// ==================== HMMA bf16x3 GEMM (scalar LDS, 64x64 warp tile) ========
// CTA tile 128x256, 8 warps (2x4), BK=32, 2-stage cp.async, occ 1.
#define GPAD     40
#define A_SUB    10240                 // 128 rows x 80 B
#define B_SUB    20480                 // 256 rows x 80 B
#define STAGE_B  (2 * A_SUB + 2 * B_SUB)   // 61440
#define GSMEM_BYTES (2 * STAGE_B)          // 122880

__global__ __launch_bounds__(256, 1) void gemm_fused(
    const __nv_bfloat16* __restrict__ Ah, const __nv_bfloat16* __restrict__ Al,
    const __nv_bfloat16* __restrict__ Bh, const __nv_bfloat16* __restrict__ Bl,
    float* __restrict__ C,
    const float* __restrict__ cf, const float* __restrict__ sf,
    __nv_bfloat16* __restrict__ Qh, __nv_bfloat16* __restrict__ Ql,
    __nv_bfloat16* __restrict__ Kh, __nv_bfloat16* __restrict__ Kl,
    __nv_bfloat16* __restrict__ Vh, __nv_bfloat16* __restrict__ Vl,
    float* __restrict__ CK, float* __restrict__ CV,
    int N, int K, int mode)
{
    extern __shared__ char sm[];
    const int tid  = threadIdx.x;
    const int wid  = tid >> 5;
    const int lane = tid & 31;
    const int g    = lane >> 2;
    const int tg   = lane & 3;
    const int wm   = wid & 1;        // 2 warp rows x 64
    const int wn   = wid >> 1;       // 4 warp cols x 64
    const int bm   = blockIdx.y << 7;     // 128 rows
    const int bn   = blockIdx.x << 8;     // 256 cols

    // smem layout per stage: [Ah|Al|Bh|Bl]
    auto load_stage = [&](int s, int k0) {
        char* base = sm + s * STAGE_B;
#pragma unroll
        for (int t = 0; t < 12; t++) {
            int id = tid + (t << 8);       // 0..3071 data chunks of 16B
            if (id < 1024) {
                int sub = id >> 9;         // 0=Ah, 1=Al
                int idx = id & 511;
                int r = idx >> 2, c = idx & 3;
                const __nv_bfloat16* src = (sub ? Al : Ah);
                cp_async16(base + sub * A_SUB + r * 80 + c * 16,
                           src + (size_t)(bm + r) * K + k0 + c * 8);
            } else {
                int sub = (id - 1024) >> 10;  // 0=Bh, 1=Bl
                int idx = (id - 1024) & 1023;
                int r = idx >> 2, c = idx & 3;
                const __nv_bfloat16* src = (sub ? Bl : Bh);
                cp_async16(base + 2 * A_SUB + sub * B_SUB + r * 80 + c * 16,
                           src + (size_t)(bn + r) * K + k0 + c * 8);
            }
        }
        CP_COMMIT();
    };

    float acc[4][8][4];
#pragma unroll
    for (int m = 0; m < 4; m++)
#pragma unroll
        for (int n = 0; n < 8; n++)
#pragma unroll
            for (int k = 0; k < 4; k++) acc[m][n][k] = 0.f;

    const int NIT = K >> 5;
    load_stage(0, 0);

    for (int it = 0; it < NIT; it++) {
        asm volatile("cp.async.wait_group 0;" ::: "memory");
        __syncthreads();
        if (it + 1 < NIT) load_stage((it + 1) & 1, (it + 1) << 5);

        const char* base = sm + (it & 1) * STAGE_B;
        const __nv_bfloat16* Ahs = (const __nv_bfloat16*)base;
        const __nv_bfloat16* Als = (const __nv_bfloat16*)(base + A_SUB);
        const __nv_bfloat16* Bhs = (const __nv_bfloat16*)(base + 2 * A_SUB);
        const __nv_bfloat16* Bls = (const __nv_bfloat16*)(base + 2 * A_SUB + B_SUB);

#pragma unroll
        for (int ks = 0; ks < 32; ks += 16) {
            uint32_t bh[8][2], bl[8][2];
#pragma unroll
            for (int n = 0; n < 8; n++) {
                int nr = wn * 64 + n * 8 + g;
                bh[n][0] = *(const uint32_t*)&Bhs[nr * GPAD + ks + 2 * tg];
                bh[n][1] = *(const uint32_t*)&Bhs[nr * GPAD + ks + 8 + 2 * tg];
                bl[n][0] = *(const uint32_t*)&Bls[nr * GPAD + ks + 2 * tg];
                bl[n][1] = *(const uint32_t*)&Bls[nr * GPAD + ks + 8 + 2 * tg];
            }
#pragma unroll
            for (int m = 0; m < 4; m++) {
                int mr = wm * 64 + m * 16;
                uint32_t ah[4], al[4];
                ah[0] = *(const uint32_t*)&Ahs[(mr + g)     * GPAD + ks + 2 * tg];
                ah[1] = *(const uint32_t*)&Ahs[(mr + 8 + g) * GPAD + ks + 2 * tg];
                ah[2] = *(const uint32_t*)&Ahs[(mr + g)     * GPAD + ks + 8 + 2 * tg];
                ah[3] = *(const uint32_t*)&Ahs[(mr + 8 + g) * GPAD + ks + 8 + 2 * tg];
                al[0] = *(const uint32_t*)&Als[(mr + g)     * GPAD + ks + 2 * tg];
                al[1] = *(const uint32_t*)&Als[(mr + 8 + g) * GPAD + ks + 2 * tg];
                al[2] = *(const uint32_t*)&Als[(mr + g)     * GPAD + ks + 8 + 2 * tg];
                al[3] = *(const uint32_t*)&Als[(mr + 8 + g) * GPAD + ks + 8 + 2 * tg];
#pragma unroll
                for (int n = 0; n < 8; n++) {
                    mma16816(acc[m][n], ah, bh[n][0], bh[n][1]);
                    mma16816(acc[m][n], ah, bl[n][0], bl[n][1]);
                    mma16816(acc[m][n], al, bh[n][0], bh[n][1]);
                }
            }
        }
        __syncthreads();
    }

    if (mode == 0) {
#pragma unroll
        for (int m = 0; m < 4; m++) {
            int r0 = bm + wm * 64 + m * 16 + g;
#pragma unroll
            for (int n = 0; n < 8; n++) {
                int col = bn + wn * 64 + n * 8 + 2 * tg;
                *(float2*)&C[(size_t)r0 * N + col] =
                    make_float2(acc[m][n][0], acc[m][n][1]);
                *(float2*)&C[(size_t)(r0 + 8) * N + col] =
                    make_float2(acc[m][n][2], acc[m][n][3]);
            }
        }
    } else if (bn < QSTRIDE) {
        // ---- Q region: rope + scale + hi/lo split ----
#pragma unroll
        for (int m = 0; m < 4; m++) {
            int r0 = bm + wm * 64 + m * 16 + g;
#pragma unroll
            for (int n = 0; n < 8; n++) {
                int col = bn + wn * 64 + n * 8 + 2 * tg;
                int d = (col & 127) >> 1;
                float cA = cf[r0 * 64 + d], sA = sf[r0 * 64 + d];
                float u0 = (acc[m][n][0] * cA - acc[m][n][1] * sA) * ATT_SCALE;
                float v0 = (acc[m][n][0] * sA + acc[m][n][1] * cA) * ATT_SCALE;
                store_hilo(Qh, Ql, (size_t)r0 * QSTRIDE + col, u0, v0);
                float cB = cf[(r0 + 8) * 64 + d], sB = sf[(r0 + 8) * 64 + d];
                float u1 = (acc[m][n][2] * cB - acc[m][n][3] * sB) * ATT_SCALE;
                float v1 = (acc[m][n][2] * sB + acc[m][n][3] * cB) * ATT_SCALE;
                store_hilo(Qh, Ql, (size_t)(r0 + 8) * QSTRIDE + col, u1, v1);
            }
        }
    } else if (bn < QSTRIDE + KSTRIDE) {
        // ---- K region: rope + cache + hi/lo split ----
#pragma unroll
        for (int m = 0; m < 4; m++) {
            int r0 = bm + wm * 64 + m * 16 + g;
#pragma unroll
            for (int n = 0; n < 8; n++) {
                int colk = bn - QSTRIDE + wn * 64 + n * 8 + 2 * tg;
                int d = (colk & 127) >> 1;
                float cA = cf[r0 * 64 + d], sA = sf[r0 * 64 + d];
                float u0 = acc[m][n][0] * cA - acc[m][n][1] * sA;
                float v0 = acc[m][n][0] * sA + acc[m][n][1] * cA;
                *(float2*)&CK[(size_t)r0 * KSTRIDE + colk] = make_float2(u0, v0);
                store_hilo(Kh, Kl, (size_t)r0 * KSTRIDE + colk, u0, v0);
                float cB = cf[(r0 + 8) * 64 + d], sB = sf[(r0 + 8) * 64 + d];
                float u1 = acc[m][n][2] * cB - acc[m][n][3] * sB;
                float v1 = acc[m][n][2] * sB + acc[m][n][3] * cB;
                *(float2*)&CK[(size_t)(r0 + 8) * KSTRIDE + colk] = make_float2(u1, v1);
                store_hilo(Kh, Kl, (size_t)(r0 + 8) * KSTRIDE + colk, u1, v1);
            }
        }
    } else {
        // ---- V region: cache + hi/lo split ----
#pragma unroll
        for (int m = 0; m < 4; m++) {
            int r0 = bm + wm * 64 + m * 16 + g;
#pragma unroll
            for (int n = 0; n < 8; n++) {
                int colv = bn - QSTRIDE - KSTRIDE + wn * 64 + n * 8 + 2 * tg;
                *(float2*)&CV[(size_t)r0 * KSTRIDE + colv] =
                    make_float2(acc[m][n][0], acc[m][n][1]);
                store_hilo(Vh, Vl, (size_t)r0 * KSTRIDE + colv,
                           acc[m][n][0], acc[m][n][1]);
                *(float2*)&CV[(size_t)(r0 + 8) * KSTRIDE + colv] =
                    make_float2(acc[m][n][2], acc[m][n][3]);
                store_hilo(Vh, Vl, (size_t)(r0 + 8) * KSTRIDE + colv,
                           acc[m][n][2], acc[m][n][3]);
            }
        }
    }
}

// ==================== cache tail ============================================
__global__ void cache_tail_kernel(const float* __restrict__ cki,
                                  const float* __restrict__ cvi,
                                  float* __restrict__ cko,
                                  float* __restrict__ cvo)
{
    int idx = blockIdx.x * blockDim.x + threadIdx.x;
    if (idx >= (WINDOW - SEQLEN) * KSTRIDE) return;
    size_t off = (size_t)SEQLEN * KSTRIDE + idx;
    cko[off] = cki[off];
    cvo[off] = cvi[off];
}

// ==================== HMMA flash attention (R10-proven version) =============
#define SPAD      136
#define Q_ELEMS   (128 * SPAD)
#define KV_ELEMS  (64 * SPAD)
#define ATT_SMEM  ((2 * Q_ELEMS + 8 * KV_ELEMS) * 2)

__global__ __launch_bounds__(256, 1) void flash_mma(
    const __nv_bfloat16* __restrict__ Qhg, const __nv_bfloat16* __restrict__ Qlg,
    const __nv_bfloat16* __restrict__ Khg, const __nv_bfloat16* __restrict__ Klg,
    const __nv_bfloat16* __restrict__ Vhg, const __nv_bfloat16* __restrict__ Vlg,
    __nv_bfloat16* __restrict__ Ohg, __nv_bfloat16* __restrict__ Olg)
{
    extern __shared__ __nv_bfloat16 sb[];
    const int tid  = threadIdx.x;
    const int wid  = tid >> 5;
    const int lane = tid & 31;
    const int g    = lane >> 2;
    const int tg   = lane & 3;
    const int qb   = (int)(gridDim.x - 1 - blockIdx.x);
    const int h    = blockIdx.y;
    const int kvh  = h >> 2;
    const int q0   = qb << 7;
    const int mr   = wid << 4;

    __nv_bfloat16* Qhs = sb;
    __nv_bfloat16* Qls = sb + Q_ELEMS;
    __nv_bfloat16* KVs = sb + 2 * Q_ELEMS;
    const uint32_t sbase = smem_u32(sb);

    {
        const __nv_bfloat16* gq[2] = { Qhg, Qlg };
#pragma unroll
        for (int i = 0; i < 16; i++) {
            int id  = tid + (i << 8);
            int tsr = id >> 11, idx = id & 2047;
            int r = idx >> 4, c = idx & 15;
            cp_async16(sb + tsr * Q_ELEMS + r * SPAD + c * 8,
                       gq[tsr] + (size_t)(q0 + r) * QSTRIDE + h * HD + c * 8);
        }
        CP_COMMIT();
    }

    const int NT = 2 * qb + 2;
    const __nv_bfloat16* gkv[4] = { Khg, Klg, Vhg, Vlg };
    auto load_kv = [&](int t, int st) {
        __nv_bfloat16* base = KVs + st * 4 * KV_ELEMS;
#pragma unroll
        for (int i = 0; i < 16; i++) {
            int id  = tid + (i << 8);
            int sub = id >> 10, idx = id & 1023;
            int r = idx >> 4, c = idx & 15;
            cp_async16(base + sub * KV_ELEMS + r * SPAD + c * 8,
                       gkv[sub] + (size_t)(t * 64 + r) * KSTRIDE + kvh * HD + c * 8);
        }
        CP_COMMIT();
    };
    load_kv(0, 0);

    float m0 = -1e30f, m1 = -1e30f, l0 = 0.f, l1 = 0.f;
    float o[16][4];
#pragma unroll
    for (int n = 0; n < 16; n++)
#pragma unroll
        for (int c = 0; c < 4; c++) o[n][c] = 0.f;

    for (int t = 0; t < NT; t++) {
        if (t + 1 < NT) {
            load_kv(t + 1, (t + 1) & 1);
            asm volatile("cp.async.wait_group 1;" ::: "memory");
        } else {
            asm volatile("cp.async.wait_group 0;" ::: "memory");
        }
        __syncthreads();

        if (t * 64 <= q0 + mr + 15) {
            const __nv_bfloat16* Khs = KVs + (t & 1) * 4 * KV_ELEMS;
            const __nv_bfloat16* Kls = Khs + KV_ELEMS;
            const uint32_t vh_base = sbase +
                (uint32_t)(2 * Q_ELEMS + (t & 1) * 4 * KV_ELEMS + 2 * KV_ELEMS) * 2;
            const uint32_t vl_base = vh_base + KV_ELEMS * 2;

            float sc[8][4];
#pragma unroll
            for (int n = 0; n < 8; n++)
#pragma unroll
                for (int c = 0; c < 4; c++) sc[n][c] = 0.f;

#pragma unroll
            for (int k = 0; k < 8; k++) {
                int ks = k << 4;
                uint32_t qh[4], ql[4];
                qh[0] = *(const uint32_t*)&Qhs[(mr + g)     * SPAD + ks + 2 * tg];
                qh[1] = *(const uint32_t*)&Qhs[(mr + 8 + g) * SPAD + ks + 2 * tg];
                qh[2] = *(const uint32_t*)&Qhs[(mr + g)     * SPAD + ks + 8 + 2 * tg];
                qh[3] = *(const uint32_t*)&Qhs[(mr + 8 + g) * SPAD + ks + 8 + 2 * tg];
                ql[0] = *(const uint32_t*)&Qls[(mr + g)     * SPAD + ks + 2 * tg];
                ql[1] = *(const uint32_t*)&Qls[(mr + 8 + g) * SPAD + ks + 2 * tg];
                ql[2] = *(const uint32_t*)&Qls[(mr + g)     * SPAD + ks + 8 + 2 * tg];
                ql[3] = *(const uint32_t*)&Qls[(mr + 8 + g) * SPAD + ks + 8 + 2 * tg];
#pragma unroll
                for (int n = 0; n < 8; n++) {
                    uint32_t kh0, kh1, kl0, kl1;
                    kh0 = *(const uint32_t*)&Khs[(8 * n + g) * SPAD + ks + 2 * tg];
                    kh1 = *(const uint32_t*)&Khs[(8 * n + g) * SPAD + ks + 8 + 2 * tg];
                    kl0 = *(const uint32_t*)&Kls[(8 * n + g) * SPAD + ks + 2 * tg];
                    kl1 = *(const uint32_t*)&Kls[(8 * n + g) * SPAD + ks + 8 + 2 * tg];
                    mma16816(sc[n], qh, kh0, kh1);
                    mma16816(sc[n], qh, kl0, kl1);
                    mma16816(sc[n], ql, kh0, kh1);
                }
            }

            const int qi0 = q0 + mr + g, qi1 = qi0 + 8;
            if (t * 64 + 63 > q0 + mr) {
#pragma unroll
                for (int n = 0; n < 8; n++) {
                    int kj = t * 64 + 8 * n + 2 * tg;
                    if (kj     > qi0) sc[n][0] = -1e30f;
                    if (kj + 1 > qi0) sc[n][1] = -1e30f;
                    if (kj     > qi1) sc[n][2] = -1e30f;
                    if (kj + 1 > qi1) sc[n][3] = -1e30f;
                }
            }

            float mt0 = -1e30f, mt1 = -1e30f;
#pragma unroll
            for (int n = 0; n < 8; n++) {
                mt0 = fmaxf(mt0, fmaxf(sc[n][0], sc[n][1]));
                mt1 = fmaxf(mt1, fmaxf(sc[n][2], sc[n][3]));
            }
            mt0 = fmaxf(mt0, __shfl_xor_sync(0xffffffffu, mt0, 1));
            mt0 = fmaxf(mt0, __shfl_xor_sync(0xffffffffu, mt0, 2));
            mt1 = fmaxf(mt1, __shfl_xor_sync(0xffffffffu, mt1, 1));
            mt1 = fmaxf(mt1, __shfl_xor_sync(0xffffffffu, mt1, 2));
            float m0n = fmaxf(m0, mt0), m1n = fmaxf(m1, mt1);
            float c0 = __expf(m0 - m0n), c1 = __expf(m1 - m1n);
            float rs0 = 0.f, rs1 = 0.f;
#pragma unroll
            for (int n = 0; n < 8; n++) {
                sc[n][0] = __expf(sc[n][0] - m0n);
                sc[n][1] = __expf(sc[n][1] - m0n);
                sc[n][2] = __expf(sc[n][2] - m1n);
                sc[n][3] = __expf(sc[n][3] - m1n);
                rs0 += sc[n][0] + sc[n][1];
                rs1 += sc[n][2] + sc[n][3];
            }
            rs0 += __shfl_xor_sync(0xffffffffu, rs0, 1);
            rs0 += __shfl_xor_sync(0xffffffffu, rs0, 2);
            rs1 += __shfl_xor_sync(0xffffffffu, rs1, 1);
            rs1 += __shfl_xor_sync(0xffffffffu, rs1, 2);
            l0 = l0 * c0 + rs0;
            l1 = l1 * c1 + rs1;
            m0 = m0n; m1 = m1n;
#pragma unroll
            for (int n = 0; n < 16; n++) {
                o[n][0] *= c0; o[n][1] *= c0; o[n][2] *= c1; o[n][3] *= c1;
            }

            uint32_t ph[4][4], pl[4][4];
#pragma unroll
            for (int j = 0; j < 4; j++) {
                const float* A = sc[2 * j];
                const float* B = sc[2 * j + 1];
                float ah0 = __bfloat162float(__float2bfloat16_rn(A[0]));
                float ah1 = __bfloat162float(__float2bfloat16_rn(A[1]));
                float ah2 = __bfloat162float(__float2bfloat16_rn(A[2]));
                float ah3 = __bfloat162float(__float2bfloat16_rn(A[3]));
                float bh0 = __bfloat162float(__float2bfloat16_rn(B[0]));
                float bh1 = __bfloat162float(__float2bfloat16_rn(B[1]));
                float bh2 = __bfloat162float(__float2bfloat16_rn(B[2]));
                float bh3 = __bfloat162float(__float2bfloat16_rn(B[3]));
                ph[j][0] = pack2(ah0, ah1);
                ph[j][1] = pack2(ah2, ah3);
                ph[j][2] = pack2(bh0, bh1);
                ph[j][3] = pack2(bh2, bh3);
                pl[j][0] = pack2(A[0] - ah0, A[1] - ah1);
                pl[j][1] = pack2(A[2] - ah2, A[3] - ah3);
                pl[j][2] = pack2(B[0] - bh0, B[1] - bh1);
                pl[j][3] = pack2(B[2] - bh2, B[3] - bh3);
            }

            const uint32_t va = (uint32_t)(((lane & 15) * SPAD + ((lane >> 4) << 3)) * 2);
#pragma unroll
            for (int j = 0; j < 4; j++) {
                const uint32_t kvoff = va + (uint32_t)(16 * j * SPAD * 2);
#pragma unroll
                for (int u = 0; u < 8; u++) {
                    uint32_t vh[4], vl[4];
                    ldsm_x4_t(vh, vh_base + kvoff + u * 32);
                    ldsm_x4_t(vl, vl_base + kvoff + u * 32);
                    mma16816(o[2 * u],     ph[j], vh[0], vh[1]);
                    mma16816(o[2 * u],     ph[j], vl[0], vl[1]);
                    mma16816(o[2 * u],     pl[j], vh[0], vh[1]);
                    mma16816(o[2 * u + 1], ph[j], vh[2], vh[3]);
                    mma16816(o[2 * u + 1], ph[j], vl[2], vl[3]);
                    mma16816(o[2 * u + 1], pl[j], vh[2], vh[3]);
                }
            }
        }
        __syncthreads();
    }

    const float inv0 = 1.f / l0, inv1 = 1.f / l1;
    const int row0 = q0 + mr + g, row1 = row0 + 8;
#pragma unroll
    for (int n = 0; n < 16; n++) {
        int col = h * HD + 8 * n + 2 * tg;
        float f00 = o[n][0] * inv0, f01 = o[n][1] * inv0;
        float f10 = o[n][2] * inv1, f11 = o[n][3] * inv1;
        store_hilo(Ohg, Olg, (size_t)row0 * QSTRIDE + col, f00, f01);
        store_hilo(Ohg, Olg, (size_t)row1 * QSTRIDE + col, f10, f11);
    }
}

// ==================== launch ================================================
extern "C" void kernel_launch(void* const* d_in, const int* in_sizes, int n_in,
                              void* d_out, int out_size)
{
    (void)in_sizes; (void)n_in; (void)out_size;
    const float* x   = (const float*)d_in[0];
    const float* cf  = (const float*)d_in[1];
    const float* sf  = (const float*)d_in[2];
    const float* cki = (const float*)d_in[5];
    const float* cvi = (const float*)d_in[6];
    const float* wq  = (const float*)d_in[7];
    const float* wk  = (const float*)d_in[8];
    const float* wv  = (const float*)d_in[9];
    const float* wo  = (const float*)d_in[10];

    float* out    = (float*)d_out;
    float* out_ck = out + (size_t)SEQLEN * DIM;
    float* out_cv = out_ck + (size_t)WINDOW * KSTRIDE;

    __nv_bfloat16 *xh, *xl, *wh, *wl, *woh, *wol, *aoh, *aol;
    __nv_bfloat16 *qh, *ql, *kh, *kl, *vh, *vl;
    cudaGetSymbolAddress((void**)&xh,  g_xh);
    cudaGetSymbolAddress((void**)&xl,  g_xl);
    cudaGetSymbolAddress((void**)&wh,  g_wh);
    cudaGetSymbolAddress((void**)&wl,  g_wl);
    cudaGetSymbolAddress((void**)&woh, g_woh);
    cudaGetSymbolAddress((void**)&wol, g_wol);
    cudaGetSymbolAddress((void**)&aoh, g_aoh);
    cudaGetSymbolAddress((void**)&aol, g_aol);
    cudaGetSymbolAddress((void**)&qh,  g_qh);
    cudaGetSymbolAddress((void**)&ql,  g_ql);
    cudaGetSymbolAddress((void**)&kh,  g_kh);
    cudaGetSymbolAddress((void**)&kl,  g_kl);
    cudaGetSymbolAddress((void**)&vh,  g_vh);
    cudaGetSymbolAddress((void**)&vl,  g_vl);

    cudaFuncSetAttribute(gemm_fused,
                         cudaFuncAttributeMaxDynamicSharedMemorySize, GSMEM_BYTES);
    cudaFuncSetAttribute(flash_mma,
                         cudaFuncAttributeMaxDynamicSharedMemorySize, ATT_SMEM);

    // merged splits: x, wq|wk|wv (packed), wo
    split_all_kernel<<<(SPLIT_TOTAL + 255) / 256, 256>>>(
        x, wq, wk, wv, wo, xh, xl, wh, wl, woh, wol);

    // fused QKV projection + rope + split + cache head (CTA tile 128x256)
    gemm_fused<<<dim3(NQKV / 256, SEQLEN / 128), 256, GSMEM_BYTES>>>(
        xh, xl, wh, wl, nullptr, cf, sf,
        qh, ql, kh, kl, vh, vl, out_ck, out_cv, NQKV, DIM, 1);

    cache_tail_kernel<<<((WINDOW - SEQLEN) * KSTRIDE) / 256, 256>>>(cki, cvi, out_ck, out_cv);

    // flash attention (R10-proven)
    flash_mma<<<dim3(SEQLEN / 128, NHEADS), 256, ATT_SMEM>>>(qh, ql, kh, kl, vh, vl, aoh, aol);

    // output projection
    gemm_fused<<<dim3(DIM / 256, SEQLEN / 128), 256, GSMEM_BYTES>>>(
        aoh, aol, woh, wol, out, nullptr, nullptr,
        nullptr, nullptr, nullptr, nullptr, nullptr, nullptr,
        nullptr, nullptr, DIM, DIM, 0);
}